// round 10
// baseline (speedup 1.0000x reference)
#include <cuda_runtime.h>
#include <cuda_fp16.h>
#include <math.h>
#include <stdint.h>

#define NC    192
#define POOLS 7
#define NPTS  196
#define NROIS 1000
#define NBATCH 4
#define DDIM  768
#define K1    9408
#define SPLITK 6

// ---------------- scratch (device globals; no runtime allocation) -----------
__device__ __half g_fT0[NBATCH * 128 * 128 * NC];   // NHWC fp16 level 0
__device__ __half g_fT1[NBATCH * 64 * 64 * NC];
__device__ __half g_fT2[NBATCH * 32 * 32 * NC];
__device__ __half g_fT3[NBATCH * 16 * 16 * NC];
__device__ __half g_ph[(size_t)NROIS * K1];   // pooled (fp16, single)
__device__ __half g_w1h[(size_t)DDIM * K1];   // w1 single fp16
__device__ __half g_w2h[DDIM * DDIM];
__device__ __half g_w2l[DDIM * DDIM];
__device__ __half g_x1h[NROIS * DDIM];
__device__ __half g_x1l[NROIS * DDIM];
__device__ float g_x2[NROIS * DDIM];
__device__ float g_part[(size_t)SPLITK * NROIS * DDIM];   // split-K partials

// ---------------- helpers ----------------------------------------------------
__device__ __forceinline__ uint32_t smem_u32(const void* p) {
    uint32_t a;
    asm("{ .reg .u64 t; cvta.to.shared.u64 t, %1; cvt.u32.u64 %0, t; }"
        : "=r"(a) : "l"(p));
    return a;
}
__device__ __forceinline__ void cp16(uint32_t s, const void* g) {
    asm volatile("cp.async.cg.shared.global [%0], [%1], 16;\n" :: "r"(s), "l"(g));
}
__device__ __forceinline__ uint32_t sw64(uint32_t o) { return o ^ ((o >> 3) & 0x30); }

__device__ __forceinline__ void ldm_x4(uint32_t* r, uint32_t addr) {
    asm volatile("ldmatrix.sync.aligned.m8n8.x4.shared.b16 {%0,%1,%2,%3}, [%4];"
                 : "=r"(r[0]), "=r"(r[1]), "=r"(r[2]), "=r"(r[3]) : "r"(addr));
}
__device__ __forceinline__ void mma16816(float* d, const uint32_t* a,
                                         const uint32_t b0, const uint32_t b1) {
    asm volatile(
        "mma.sync.aligned.m16n8k16.row.col.f32.f16.f16.f32 "
        "{%0,%1,%2,%3}, {%4,%5,%6,%7}, {%8,%9}, {%0,%1,%2,%3};"
        : "+f"(d[0]), "+f"(d[1]), "+f"(d[2]), "+f"(d[3])
        : "r"(a[0]), "r"(a[1]), "r"(a[2]), "r"(a[3]), "r"(b0), "r"(b1));
}

// ---------------- NCHW fp32 -> NHWC fp16 transpose ---------------------------
__global__ __launch_bounds__(256) void transpose_nchw_nhwc(
    const float* __restrict__ in, __half* __restrict__ out, int H, int W) {
    __shared__ float tile[32][33];
    int by = blockIdx.z;
    int b = by / H, y = by % H;
    int c0 = blockIdx.y * 32;
    int x0 = blockIdx.x * 32;
    const float* inp = in + ((size_t)b * NC) * H * W + (size_t)y * W;
    for (int i = threadIdx.y; i < 32; i += 8) {
        int c = c0 + i, x = x0 + threadIdx.x;
        float v = 0.f;
        if (c < NC && x < W) v = inp[(size_t)c * H * W + x];
        tile[i][threadIdx.x] = v;
    }
    __syncthreads();
    __half* outp = out + ((size_t)(b * H + y) * W) * NC;
    for (int i = threadIdx.y; i < 32; i += 8) {
        int x = x0 + i, c = c0 + threadIdx.x;
        if (c < NC && x < W) outp[(size_t)x * NC + c] = __float2half_rn(tile[threadIdx.x][i]);
    }
}

// ---------------- fp32 -> fp16 single round (x2 vectorized) -----------------
__global__ __launch_bounds__(256) void round_half_kernel(
    const float* __restrict__ in, __half* __restrict__ hi, int n2) {
    int i = blockIdx.x * 256 + threadIdx.x;
    if (i < n2) {
        float2 v = ((const float2*)in)[i];
        __half2 hh; hh.x = __float2half_rn(v.x); hh.y = __float2half_rn(v.y);
        ((__half2*)hi)[i] = hh;
    }
}

// ---------------- fp32 -> (fp16 hi, fp16 lo) split (x2 vectorized) ----------
__global__ __launch_bounds__(256) void split_kernel(
    const float* __restrict__ in, __half* __restrict__ hi,
    __half* __restrict__ lo, int n2) {
    int i = blockIdx.x * 256 + threadIdx.x;
    if (i < n2) {
        float2 v = ((const float2*)in)[i];
        __half h0 = __float2half_rn(v.x);
        __half h1 = __float2half_rn(v.y);
        __half2 hh; hh.x = h0; hh.y = h1;
        __half2 ll;
        ll.x = __float2half_rn(v.x - __half2float(h0));
        ll.y = __float2half_rn(v.y - __half2float(h1));
        ((__half2*)hi)[i] = hh;
        ((__half2*)lo)[i] = ll;
    }
}

// ---------------- RoIAlign (fp16 NHWC source) --------------------------------
__global__ __launch_bounds__(192) void roialign_kernel(const float* __restrict__ rois) {
    __shared__ int   s_off[NPTS][4];
    __shared__ float s_w[NPTS][4];
    __shared__ float s_out[K1];

    int n = blockIdx.x;
    float ry1 = rois[n * 5 + 0], rx1 = rois[n * 5 + 1];
    float ry2 = rois[n * 5 + 2], rx2 = rois[n * 5 + 3];
    int bix = (int)rois[n * 5 + 4];

    float h = ry2 - ry1, w = rx2 - rx1;
    float lvlf = rintf(4.0f + 0.5f * log2f(h * w));
    int lvl = min(max((int)lvlf, 0), 3);

    int H, W;
    const __half* fm;
    if (lvl == 0)      { H = 128; W = 128; fm = g_fT0; }
    else if (lvl == 1) { H = 64;  W = 64;  fm = g_fT1; }
    else if (lvl == 2) { H = 32;  W = 32;  fm = g_fT2; }
    else               { H = 16;  W = 16;  fm = g_fT3; }

    float Y1 = ry1 * H, X1 = rx1 * W, Y2 = ry2 * H, X2 = rx2 * W;
    float bin_h = fmaxf(Y2 - Y1, 1.0f) * (1.0f / POOLS);
    float bin_w = fmaxf(X2 - X1, 1.0f) * (1.0f / POOLS);

    for (int p = threadIdx.x; p < NPTS; p += blockDim.x) {
        int gy = p / 14, gx = p % 14;
        float grid_y = (float)(gy >> 1) + ((float)(gy & 1) + 0.5f) * 0.5f;
        float grid_x = (float)(gx >> 1) + ((float)(gx & 1) + 0.5f) * 0.5f;
        float y = Y1 + grid_y * bin_h;
        float x = X1 + grid_x * bin_w;
        bool valid = (y >= -1.0f) && (y <= (float)H) && (x >= -1.0f) && (x <= (float)W);
        y = fminf(fmaxf(y, 0.f), (float)(H - 1));
        x = fminf(fmaxf(x, 0.f), (float)(W - 1));
        int y0 = (int)floorf(y);
        int x0 = (int)floorf(x);
        int y1i = min(y0 + 1, H - 1);
        int x1i = min(x0 + 1, W - 1);
        float ly = y - (float)y0, lx = x - (float)x0;
        float vmul = valid ? 0.25f : 0.0f;
        int rowb = bix * H;
        s_off[p][0] = ((rowb + y0)  * W + x0)  * NC;
        s_off[p][1] = ((rowb + y0)  * W + x1i) * NC;
        s_off[p][2] = ((rowb + y1i) * W + x0)  * NC;
        s_off[p][3] = ((rowb + y1i) * W + x1i) * NC;
        s_w[p][0] = (1.f - ly) * (1.f - lx) * vmul;
        s_w[p][1] = (1.f - ly) * lx * vmul;
        s_w[p][2] = ly * (1.f - lx) * vmul;
        s_w[p][3] = ly * lx * vmul;
    }
    __syncthreads();

    int c = threadIdx.x;
    #pragma unroll
    for (int by = 0; by < POOLS; by++) {
        #pragma unroll
        for (int bx = 0; bx < POOLS; bx++) {
            float acc = 0.f;
            #pragma unroll
            for (int sy = 0; sy < 2; sy++) {
                #pragma unroll
                for (int sx = 0; sx < 2; sx++) {
                    int p = (by * 2 + sy) * 14 + (bx * 2 + sx);
                    acc += s_w[p][0] * __half2float(fm[s_off[p][0] + c])
                         + s_w[p][1] * __half2float(fm[s_off[p][1] + c])
                         + s_w[p][2] * __half2float(fm[s_off[p][2] + c])
                         + s_w[p][3] * __half2float(fm[s_off[p][3] + c]);
                }
            }
            s_out[c * 49 + by * POOLS + bx] = acc;
        }
    }
    __syncthreads();
    __half* dh = g_ph + (size_t)n * K1;
    for (int i = threadIdx.x; i < K1; i += blockDim.x) {
        dh[i] = __float2half_rn(s_out[i]);
    }
}

// ---------------- mma.sync split-K GEMM partial: P = A * B^T -----------------
// TERMS==1: A,B single fp16 (1 MMA / frag).  TERMS==3: A,B (hi,lo), 3 MMAs.
// CTA tile 128x256 (warp tile 64x64, 8 warps 2x4), BK=32, 3-stage cp.async.
#define NSTAGE 3

template <int TERMS>
__global__ __launch_bounds__(256, 1) void gemm_mma_sk(
    const __half* __restrict__ Ahi, const __half* __restrict__ Alo,
    const __half* __restrict__ Bhi, const __half* __restrict__ Blo,
    float* __restrict__ Pf, int M, int N, int K, int kLen) {
    constexpr uint32_t ST_AH = 0;
    constexpr uint32_t ST_AL = 8192;                         // TERMS==3 only
    constexpr uint32_t ST_BH = (TERMS == 3) ? 16384 : 8192;
    constexpr uint32_t ST_BL = 32768;                        // TERMS==3 only
    constexpr uint32_t STAGE_BYTES = (TERMS == 3) ? 49152 : 24576;
    extern __shared__ char dynsmem[];
    uint32_t sb0 = smem_u32(dynsmem);

    int tid = threadIdx.x;
    int lane = tid & 31, wid = tid >> 5;
    int wm = wid >> 2, wn = wid & 3;     // 2 x 4 warp grid, warp tile 64x64
    int m0 = blockIdx.y * 128, n0 = blockIdx.x * 256;
    int kBase = blockIdx.z * kLen;

    // --- cp.async source setup ------------------------------------------------
    int arow_l = tid >> 1;
    int lc = (tid & 1) * 2;
    int arow = min(m0 + arow_l, M - 1);
    const char* gAh = (const char*)(Ahi + (size_t)arow * K + kBase);
    const char* gAl = (TERMS == 3) ? (const char*)(Alo + (size_t)arow * K + kBase) : nullptr;
    const char* gBh = (const char*)(Bhi + (size_t)(n0 + tid) * K + kBase);
    const char* gBl = (TERMS == 3) ? (const char*)(Blo + (size_t)(n0 + tid) * K + kBase) : nullptr;
    uint32_t soA0 = sw64((uint32_t)(arow_l * 64 + lc * 16));
    uint32_t soA1 = sw64((uint32_t)(arow_l * 64 + (lc + 1) * 16));
    uint32_t soB[4];
    #pragma unroll
    for (int c = 0; c < 4; c++) soB[c] = sw64((uint32_t)(tid * 64 + c * 16));

    int nk = kLen >> 5;   // kLen / 32

    auto load_stage = [&](int j) {
        uint32_t sb = sb0 + (uint32_t)(j % NSTAGE) * STAGE_BYTES;
        int gbA = (j << 6) + (lc << 4);
        int gbB = (j << 6);
        cp16(sb + ST_AH + soA0, gAh + gbA);
        cp16(sb + ST_AH + soA1, gAh + gbA + 16);
        if (TERMS == 3) {
            cp16(sb + ST_AL + soA0, gAl + gbA);
            cp16(sb + ST_AL + soA1, gAl + gbA + 16);
        }
        #pragma unroll
        for (int c = 0; c < 4; c++) {
            cp16(sb + ST_BH + soB[c], gBh + gbB + c * 16);
            if (TERMS == 3) cp16(sb + ST_BL + soB[c], gBl + gbB + c * 16);
        }
        asm volatile("cp.async.commit_group;\n" ::);
    };

    // --- ldmatrix per-thread offsets (within-tile, swizzled) -----------------
    int half = lane >> 4;
    int lr = lane & 15;
    uint32_t offA[4][2], offB[4][2];
    #pragma unroll
    for (int mt = 0; mt < 4; mt++)
        #pragma unroll
        for (int s = 0; s < 2; s++)
            offA[mt][s] = sw64((uint32_t)((wm * 64 + mt * 16 + lr) * 64 + (s * 2 + half) * 16));
    #pragma unroll
    for (int pr = 0; pr < 4; pr++)
        #pragma unroll
        for (int s = 0; s < 2; s++)
            offB[pr][s] = sw64((uint32_t)((wn * 64 + pr * 16 + lr) * 64 + (s * 2 + half) * 16));

    float acc[4][8][4];
    #pragma unroll
    for (int a = 0; a < 4; a++)
        #pragma unroll
        for (int b = 0; b < 8; b++)
            #pragma unroll
            for (int c = 0; c < 4; c++) acc[a][b][c] = 0.f;

    load_stage(0);
    load_stage(1);

    for (int i = 0; i < nk; i++) {
        if (i + 1 < nk) asm volatile("cp.async.wait_group 1;\n" ::);
        else            asm volatile("cp.async.wait_group 0;\n" ::);
        __syncthreads();
        if (i + 2 < nk) load_stage(i + 2);

        uint32_t sb = sb0 + (uint32_t)(i % NSTAGE) * STAGE_BYTES;
        #pragma unroll
        for (int s = 0; s < 2; s++) {
            uint32_t ah[4][4], al[4][4];
            uint32_t bh[8][2], bl[8][2];
            #pragma unroll
            for (int mt = 0; mt < 4; mt++) {
                ldm_x4(ah[mt], sb + ST_AH + offA[mt][s]);
                if (TERMS == 3) ldm_x4(al[mt], sb + ST_AL + offA[mt][s]);
            }
            #pragma unroll
            for (int pr = 0; pr < 4; pr++) {
                uint32_t t4[4];
                ldm_x4(t4, sb + ST_BH + offB[pr][s]);
                bh[pr * 2][0] = t4[0]; bh[pr * 2][1] = t4[2];
                bh[pr * 2 + 1][0] = t4[1]; bh[pr * 2 + 1][1] = t4[3];
                if (TERMS == 3) {
                    ldm_x4(t4, sb + ST_BL + offB[pr][s]);
                    bl[pr * 2][0] = t4[0]; bl[pr * 2][1] = t4[2];
                    bl[pr * 2 + 1][0] = t4[1]; bl[pr * 2 + 1][1] = t4[3];
                }
            }
            #pragma unroll
            for (int mt = 0; mt < 4; mt++)
                #pragma unroll
                for (int nt = 0; nt < 8; nt++) {
                    mma16816(acc[mt][nt], ah[mt], bh[nt][0], bh[nt][1]);
                    if (TERMS == 3) {
                        mma16816(acc[mt][nt], al[mt], bh[nt][0], bh[nt][1]);
                        mma16816(acc[mt][nt], ah[mt], bl[nt][0], bl[nt][1]);
                    }
                }
        }
    }

    // --- epilogue: store fp32 partials ---------------------------------------
    float* P = Pf + (size_t)blockIdx.z * M * N;
    int qr = lane >> 2, qc = (lane & 3) * 2;
    #pragma unroll
    for (int mt = 0; mt < 4; mt++) {
        int mlo = m0 + wm * 64 + mt * 16 + qr;
        #pragma unroll
        for (int nt = 0; nt < 8; nt++) {
            int nn = n0 + wn * 64 + nt * 8 + qc;
            if (mlo < M) {
                float2 vv; vv.x = acc[mt][nt][0]; vv.y = acc[mt][nt][1];
                *(float2*)(P + (size_t)mlo * N + nn) = vv;
            }
            if (mlo + 8 < M) {
                float2 vv; vv.x = acc[mt][nt][2]; vv.y = acc[mt][nt][3];
                *(float2*)(P + (size_t)(mlo + 8) * N + nn) = vv;
            }
        }
    }
}

// ---------------- split-K reduce: sum partials + bias + relu -----------------
template <int WRITE_SPLIT>
__global__ __launch_bounds__(256) void reduce_sk(
    const float* __restrict__ P, const float* __restrict__ bias,
    float* __restrict__ Cf, __half* __restrict__ Chi,
    __half* __restrict__ Clo, int MN, int N) {
    int i = blockIdx.x * 256 + threadIdx.x;
    if (i >= MN) return;
    float v = __ldg(bias + (i % N));
    #pragma unroll
    for (int z = 0; z < SPLITK; z++) v += P[(size_t)z * MN + i];
    v = fmaxf(v, 0.f);
    if (WRITE_SPLIT) {
        __half h = __float2half_rn(v);
        Chi[i] = h;
        Clo[i] = __float2half_rn(v - __half2float(h));
    } else {
        Cf[i] = v;
    }
}

// ---------------- heads ------------------------------------------------------
__global__ __launch_bounds__(448) void heads_kernel(
    const float* __restrict__ wb, const float* __restrict__ bb,
    const float* __restrict__ wc, const float* __restrict__ bc,
    const float* __restrict__ wr, const float* __restrict__ br,
    const float* __restrict__ wu, const float* __restrict__ bu,
    float* __restrict__ out) {
    __shared__ float xs[DDIM];
    int n = blockIdx.x;
    for (int i = threadIdx.x; i < DDIM; i += blockDim.x) xs[i] = g_x2[n * DDIM + i];
    __syncthreads();
    int wid = threadIdx.x >> 5, lane = threadIdx.x & 31;
    const float* wrow;
    float bv;
    if (wid < 8)       { wrow = wb + wid * DDIM;        bv = bb[wid]; }
    else if (wid < 10) { wrow = wc + (wid - 8) * DDIM;  bv = bc[wid - 8]; }
    else if (wid < 12) { wrow = wr + (wid - 10) * DDIM; bv = br[wid - 10]; }
    else               { wrow = wu + (wid - 12) * DDIM; bv = bu[wid - 12]; }
    float s = 0.f;
    for (int i = lane; i < DDIM; i += 32) s += xs[i] * wrow[i];
    #pragma unroll
    for (int o = 16; o; o >>= 1) s += __shfl_down_sync(0xffffffff, s, o);
    if (lane == 0) {
        float v = s + bv;
        if (wid < 8)       out[n * 8 + wid] = v;
        else if (wid < 10) out[8000 + n * 2 + (wid - 8)] = v;
        else if (wid < 12) out[10000 + n * 4 + (wid - 10) * 2 + 0] = v;
        else               out[10000 + n * 4 + (wid - 12) * 2 + 1] = v;
    }
}

// ---------------- host launcher ---------------------------------------------
extern "C" void kernel_launch(void* const* d_in, const int* in_sizes, int n_in,
                              void* d_out, int out_size) {
    const float* fmap0 = (const float*)d_in[0];
    const float* fmap1 = (const float*)d_in[1];
    const float* fmap2 = (const float*)d_in[2];
    const float* fmap3 = (const float*)d_in[3];
    const float* rois  = (const float*)d_in[4];
    const float* w1    = (const float*)d_in[5];
    const float* b1    = (const float*)d_in[6];
    const float* w2    = (const float*)d_in[7];
    const float* b2    = (const float*)d_in[8];
    const float* wbbox = (const float*)d_in[9];
    const float* bbbox = (const float*)d_in[10];
    const float* wcls  = (const float*)d_in[11];
    const float* bcls  = (const float*)d_in[12];
    const float* wreg  = (const float*)d_in[13];
    const float* breg  = (const float*)d_in[14];
    const float* wunc  = (const float*)d_in[15];
    const float* bunc  = (const float*)d_in[16];
    float* out = (float*)d_out;

    __half* fT0;  cudaGetSymbolAddress((void**)&fT0, g_fT0);
    __half* fT1;  cudaGetSymbolAddress((void**)&fT1, g_fT1);
    __half* fT2;  cudaGetSymbolAddress((void**)&fT2, g_fT2);
    __half* fT3;  cudaGetSymbolAddress((void**)&fT3, g_fT3);
    __half *ph, *w1h, *w2h, *w2l, *x1h, *x1l;
    cudaGetSymbolAddress((void**)&ph,  g_ph);
    cudaGetSymbolAddress((void**)&w1h, g_w1h);
    cudaGetSymbolAddress((void**)&w2h, g_w2h);
    cudaGetSymbolAddress((void**)&w2l, g_w2l);
    cudaGetSymbolAddress((void**)&x1h, g_x1h);
    cudaGetSymbolAddress((void**)&x1l, g_x1l);
    float* x2;   cudaGetSymbolAddress((void**)&x2, g_x2);
    float* part; cudaGetSymbolAddress((void**)&part, g_part);

    cudaFuncSetAttribute(gemm_mma_sk<1>, cudaFuncAttributeMaxDynamicSharedMemorySize, NSTAGE * 24576);
    cudaFuncSetAttribute(gemm_mma_sk<3>, cudaFuncAttributeMaxDynamicSharedMemorySize, NSTAGE * 49152);

    // weight prep: w1 -> single fp16, w2 -> fp16 hi/lo
    {
        int n1 = DDIM * K1 / 2;
        round_half_kernel<<<(n1 + 255) / 256, 256>>>(w1, w1h, n1);
        int n2 = DDIM * DDIM / 2;
        split_kernel<<<(n2 + 255) / 256, 256>>>(w2, w2h, w2l, n2);
    }

    dim3 tb(32, 8);
    transpose_nchw_nhwc<<<dim3(4, 6, NBATCH * 128), tb>>>(fmap0, fT0, 128, 128);
    transpose_nchw_nhwc<<<dim3(2, 6, NBATCH * 64),  tb>>>(fmap1, fT1, 64, 64);
    transpose_nchw_nhwc<<<dim3(1, 6, NBATCH * 32),  tb>>>(fmap2, fT2, 32, 32);
    transpose_nchw_nhwc<<<dim3(1, 6, NBATCH * 16),  tb>>>(fmap3, fT3, 16, 16);

    roialign_kernel<<<NROIS, 192>>>(rois);

    const int MN = NROIS * DDIM;
    // FC1: single-term fp16 GEMM, split-K=6.
    gemm_mma_sk<1><<<dim3(DDIM / 256, (NROIS + 127) / 128, SPLITK), 256, NSTAGE * 24576>>>(
        ph, nullptr, w1h, nullptr, part, NROIS, DDIM, K1, K1 / SPLITK);
    reduce_sk<1><<<(MN + 255) / 256, 256>>>(part, b1, nullptr, x1h, x1l, MN, DDIM);

    // FC2: 3-term fp16 split GEMM, split-K=6.
    gemm_mma_sk<3><<<dim3(DDIM / 256, (NROIS + 127) / 128, SPLITK), 256, NSTAGE * 49152>>>(
        x1h, x1l, w2h, w2l, part, NROIS, DDIM, DDIM, DDIM / SPLITK);
    reduce_sk<0><<<(MN + 255) / 256, 256>>>(part, b2, x2, nullptr, nullptr, MN, DDIM);

    heads_kernel<<<NROIS, 448>>>(wbbox, bbbox, wcls, bcls, wreg, breg, wunc, bunc, out);
}

// round 14
// speedup vs baseline: 1.1816x; 1.1816x over previous
#include <cuda_runtime.h>
#include <cuda_fp16.h>
#include <math.h>
#include <stdint.h>

#define NC    192
#define POOLS 7
#define NPTS  196
#define NROIS 1000
#define NBATCH 4
#define DDIM  768
#define K1    9408
#define SPLITK 6

// ---------------- scratch (device globals; no runtime allocation) -----------
__device__ __half g_fT0[NBATCH * 128 * 128 * NC];   // NHWC fp16 level 0
__device__ __half g_fT1[NBATCH * 64 * 64 * NC];
__device__ __half g_fT2[NBATCH * 32 * 32 * NC];
__device__ __half g_fT3[NBATCH * 16 * 16 * NC];
__device__ __half g_ph[(size_t)NROIS * K1];   // pooled (fp16, single)
__device__ __half g_w1h[(size_t)DDIM * K1];   // w1 single fp16
__device__ __half g_w2h[DDIM * DDIM];
__device__ __half g_w2l[DDIM * DDIM];
__device__ __half g_x1h[NROIS * DDIM];
__device__ __half g_x1l[NROIS * DDIM];
__device__ float g_part[(size_t)SPLITK * NROIS * DDIM];   // split-K partials

// ---------------- helpers ----------------------------------------------------
__device__ __forceinline__ uint32_t smem_u32(const void* p) {
    uint32_t a;
    asm("{ .reg .u64 t; cvta.to.shared.u64 t, %1; cvt.u32.u64 %0, t; }"
        : "=r"(a) : "l"(p));
    return a;
}
__device__ __forceinline__ void cp16(uint32_t s, const void* g) {
    asm volatile("cp.async.cg.shared.global [%0], [%1], 16;\n" :: "r"(s), "l"(g));
}
__device__ __forceinline__ uint32_t sw64(uint32_t o) { return o ^ ((o >> 3) & 0x30); }

__device__ __forceinline__ void ldm_x4(uint32_t* r, uint32_t addr) {
    asm volatile("ldmatrix.sync.aligned.m8n8.x4.shared.b16 {%0,%1,%2,%3}, [%4];"
                 : "=r"(r[0]), "=r"(r[1]), "=r"(r[2]), "=r"(r[3]) : "r"(addr));
}
__device__ __forceinline__ void mma16816(float* d, const uint32_t* a,
                                         const uint32_t b0, const uint32_t b1) {
    asm volatile(
        "mma.sync.aligned.m16n8k16.row.col.f32.f16.f16.f32 "
        "{%0,%1,%2,%3}, {%4,%5,%6,%7}, {%8,%9}, {%0,%1,%2,%3};"
        : "+f"(d[0]), "+f"(d[1]), "+f"(d[2]), "+f"(d[3])
        : "r"(a[0]), "r"(a[1]), "r"(a[2]), "r"(a[3]), "r"(b0), "r"(b1));
}

// ---------------- NCHW fp32 -> NHWC fp16 transpose ---------------------------
__global__ __launch_bounds__(256) void transpose_nchw_nhwc(
    const float* __restrict__ in, __half* __restrict__ out, int H, int W) {
    __shared__ float tile[32][33];
    int by = blockIdx.z;
    int b = by / H, y = by % H;
    int c0 = blockIdx.y * 32;
    int x0 = blockIdx.x * 32;
    const float* inp = in + ((size_t)b * NC) * H * W + (size_t)y * W;
    for (int i = threadIdx.y; i < 32; i += 8) {
        int c = c0 + i, x = x0 + threadIdx.x;
        float v = 0.f;
        if (c < NC && x < W) v = inp[(size_t)c * H * W + x];
        tile[i][threadIdx.x] = v;
    }
    __syncthreads();
    __half* outp = out + ((size_t)(b * H + y) * W) * NC;
    for (int i = threadIdx.y; i < 32; i += 8) {
        int x = x0 + i, c = c0 + threadIdx.x;
        if (c < NC && x < W) outp[(size_t)x * NC + c] = __float2half_rn(tile[threadIdx.x][i]);
    }
}

// ---------------- fp32 -> fp16 single round (x2 vectorized) -----------------
__global__ __launch_bounds__(256) void round_half_kernel(
    const float* __restrict__ in, __half* __restrict__ hi, int n2) {
    int i = blockIdx.x * 256 + threadIdx.x;
    if (i < n2) {
        float2 v = ((const float2*)in)[i];
        __half2 hh; hh.x = __float2half_rn(v.x); hh.y = __float2half_rn(v.y);
        ((__half2*)hi)[i] = hh;
    }
}

// ---------------- fp32 -> (fp16 hi, fp16 lo) split (x2 vectorized) ----------
__global__ __launch_bounds__(256) void split_kernel(
    const float* __restrict__ in, __half* __restrict__ hi,
    __half* __restrict__ lo, int n2) {
    int i = blockIdx.x * 256 + threadIdx.x;
    if (i < n2) {
        float2 v = ((const float2*)in)[i];
        __half h0 = __float2half_rn(v.x);
        __half h1 = __float2half_rn(v.y);
        __half2 hh; hh.x = h0; hh.y = h1;
        __half2 ll;
        ll.x = __float2half_rn(v.x - __half2float(h0));
        ll.y = __float2half_rn(v.y - __half2float(h1));
        ((__half2*)hi)[i] = hh;
        ((__half2*)lo)[i] = ll;
    }
}

// ---------------- RoIAlign (fp16 NHWC, half2 channel pairs) ------------------
// 192 threads = 96 channel-pairs x 2 bin-halves (bins 0-24 / 25-48).
__global__ __launch_bounds__(192) void roialign_kernel(const float* __restrict__ rois) {
    __shared__ int   s_off[NPTS][4];
    __shared__ float s_w[NPTS][4];
    __shared__ float s_out[K1];

    int n = blockIdx.x;
    float ry1 = rois[n * 5 + 0], rx1 = rois[n * 5 + 1];
    float ry2 = rois[n * 5 + 2], rx2 = rois[n * 5 + 3];
    int bix = (int)rois[n * 5 + 4];

    float h = ry2 - ry1, w = rx2 - rx1;
    float lvlf = rintf(4.0f + 0.5f * log2f(h * w));
    int lvl = min(max((int)lvlf, 0), 3);

    int H, W;
    const __half* fm;
    if (lvl == 0)      { H = 128; W = 128; fm = g_fT0; }
    else if (lvl == 1) { H = 64;  W = 64;  fm = g_fT1; }
    else if (lvl == 2) { H = 32;  W = 32;  fm = g_fT2; }
    else               { H = 16;  W = 16;  fm = g_fT3; }
    const __half2* fm2 = (const __half2*)fm;

    float Y1 = ry1 * H, X1 = rx1 * W, Y2 = ry2 * H, X2 = rx2 * W;
    float bin_h = fmaxf(Y2 - Y1, 1.0f) * (1.0f / POOLS);
    float bin_w = fmaxf(X2 - X1, 1.0f) * (1.0f / POOLS);

    for (int p = threadIdx.x; p < NPTS; p += blockDim.x) {
        int gy = p / 14, gx = p % 14;
        float grid_y = (float)(gy >> 1) + ((float)(gy & 1) + 0.5f) * 0.5f;
        float grid_x = (float)(gx >> 1) + ((float)(gx & 1) + 0.5f) * 0.5f;
        float y = Y1 + grid_y * bin_h;
        float x = X1 + grid_x * bin_w;
        bool valid = (y >= -1.0f) && (y <= (float)H) && (x >= -1.0f) && (x <= (float)W);
        y = fminf(fmaxf(y, 0.f), (float)(H - 1));
        x = fminf(fmaxf(x, 0.f), (float)(W - 1));
        int y0 = (int)floorf(y);
        int x0 = (int)floorf(x);
        int y1i = min(y0 + 1, H - 1);
        int x1i = min(x0 + 1, W - 1);
        float ly = y - (float)y0, lx = x - (float)x0;
        float vmul = valid ? 0.25f : 0.0f;
        int rowb = bix * H;
        // offsets in half2 units (96 channel pairs per pixel)
        s_off[p][0] = ((rowb + y0)  * W + x0)  * (NC / 2);
        s_off[p][1] = ((rowb + y0)  * W + x1i) * (NC / 2);
        s_off[p][2] = ((rowb + y1i) * W + x0)  * (NC / 2);
        s_off[p][3] = ((rowb + y1i) * W + x1i) * (NC / 2);
        s_w[p][0] = (1.f - ly) * (1.f - lx) * vmul;
        s_w[p][1] = (1.f - ly) * lx * vmul;
        s_w[p][2] = ly * (1.f - lx) * vmul;
        s_w[p][3] = ly * lx * vmul;
    }
    __syncthreads();

    int cpair = threadIdx.x % 96;
    int bhalf = threadIdx.x / 96;          // 0: bins 0-24, 1: bins 25-48
    int bin0 = bhalf ? 25 : 0;
    int bin1 = bhalf ? 49 : 25;
    int c0 = cpair * 2;
    for (int bin = bin0; bin < bin1; bin++) {
        int by = bin / POOLS, bx = bin % POOLS;
        float ax = 0.f, ay = 0.f;
        #pragma unroll
        for (int sy = 0; sy < 2; sy++) {
            #pragma unroll
            for (int sx = 0; sx < 2; sx++) {
                int p = (by * 2 + sy) * 14 + (bx * 2 + sx);
                #pragma unroll
                for (int q = 0; q < 4; q++) {
                    float2 f = __half22float2(fm2[s_off[p][q] + cpair]);
                    float wq = s_w[p][q];
                    ax += wq * f.x;
                    ay += wq * f.y;
                }
            }
        }
        s_out[c0 * 49 + bin] = ax;
        s_out[(c0 + 1) * 49 + bin] = ay;
    }
    __syncthreads();
    __half* dh = g_ph + (size_t)n * K1;
    for (int i = threadIdx.x; i < K1; i += blockDim.x) {
        dh[i] = __float2half_rn(s_out[i]);
    }
}

// ---------------- FC1 GEMM: 128x128 tile, 2 CTAs/SM, single fp16 term --------
// 8 warps as 4(M) x 2(N); warp tile 32x64. BK=32, 3-stage cp.async.
#define NSTAGE 3
#define F1_STAGE 16384   // A 8KB + B 8KB

__global__ __launch_bounds__(256, 2) void gemm_fc1(
    const __half* __restrict__ A, const __half* __restrict__ B,
    float* __restrict__ Pf, int M, int N, int K, int kLen) {
    extern __shared__ char dynsmem[];
    uint32_t sb0 = smem_u32(dynsmem);

    int tid = threadIdx.x;
    int lane = tid & 31, wid = tid >> 5;
    int wm = wid >> 1, wn = wid & 1;     // 4 x 2 warp grid, warp tile 32x64
    int m0 = blockIdx.y * 128, n0 = blockIdx.x * 128;
    int kBase = blockIdx.z * kLen;

    int lrow = tid >> 1;
    int lc = (tid & 1) * 2;
    int arow = min(m0 + lrow, M - 1);
    const char* gA = (const char*)(A + (size_t)arow * K + kBase);
    const char* gB = (const char*)(B + (size_t)(n0 + lrow) * K + kBase);
    uint32_t so0 = sw64((uint32_t)(lrow * 64 + lc * 16));
    uint32_t so1 = sw64((uint32_t)(lrow * 64 + (lc + 1) * 16));

    int nk = kLen >> 5;

    auto load_stage = [&](int j) {
        uint32_t sb = sb0 + (uint32_t)(j % NSTAGE) * F1_STAGE;
        int gb = (j << 6) + (lc << 4);
        cp16(sb + so0, gA + gb);
        cp16(sb + so1, gA + gb + 16);
        cp16(sb + 8192 + so0, gB + gb);
        cp16(sb + 8192 + so1, gB + gb + 16);
        asm volatile("cp.async.commit_group;\n" ::);
    };

    int half = lane >> 4;
    int lr = lane & 15;
    uint32_t offA[2][2], offB[4][2];
    #pragma unroll
    for (int mt = 0; mt < 2; mt++)
        #pragma unroll
        for (int s = 0; s < 2; s++)
            offA[mt][s] = sw64((uint32_t)((wm * 32 + mt * 16 + lr) * 64 + (s * 2 + half) * 16));
    #pragma unroll
    for (int pr = 0; pr < 4; pr++)
        #pragma unroll
        for (int s = 0; s < 2; s++)
            offB[pr][s] = sw64((uint32_t)((wn * 64 + pr * 16 + lr) * 64 + (s * 2 + half) * 16));

    float acc[2][8][4];
    #pragma unroll
    for (int a = 0; a < 2; a++)
        #pragma unroll
        for (int b = 0; b < 8; b++)
            #pragma unroll
            for (int c = 0; c < 4; c++) acc[a][b][c] = 0.f;

    load_stage(0);
    load_stage(1);

    for (int i = 0; i < nk; i++) {
        if (i + 1 < nk) asm volatile("cp.async.wait_group 1;\n" ::);
        else            asm volatile("cp.async.wait_group 0;\n" ::);
        __syncthreads();
        if (i + 2 < nk) load_stage(i + 2);

        uint32_t sb = sb0 + (uint32_t)(i % NSTAGE) * F1_STAGE;
        #pragma unroll
        for (int s = 0; s < 2; s++) {
            uint32_t ah[2][4], bh[8][2];
            #pragma unroll
            for (int mt = 0; mt < 2; mt++)
                ldm_x4(ah[mt], sb + offA[mt][s]);
            #pragma unroll
            for (int pr = 0; pr < 4; pr++) {
                uint32_t t4[4];
                ldm_x4(t4, sb + 8192 + offB[pr][s]);
                bh[pr * 2][0] = t4[0]; bh[pr * 2][1] = t4[2];
                bh[pr * 2 + 1][0] = t4[1]; bh[pr * 2 + 1][1] = t4[3];
            }
            #pragma unroll
            for (int mt = 0; mt < 2; mt++)
                #pragma unroll
                for (int nt = 0; nt < 8; nt++)
                    mma16816(acc[mt][nt], ah[mt], bh[nt][0], bh[nt][1]);
        }
    }

    float* P = Pf + (size_t)blockIdx.z * M * N;
    int qr = lane >> 2, qc = (lane & 3) * 2;
    #pragma unroll
    for (int mt = 0; mt < 2; mt++) {
        int mlo = m0 + wm * 32 + mt * 16 + qr;
        #pragma unroll
        for (int nt = 0; nt < 8; nt++) {
            int nn = n0 + wn * 64 + nt * 8 + qc;
            if (mlo < M) {
                float2 vv; vv.x = acc[mt][nt][0]; vv.y = acc[mt][nt][1];
                *(float2*)(P + (size_t)mlo * N + nn) = vv;
            }
            if (mlo + 8 < M) {
                float2 vv; vv.x = acc[mt][nt][2]; vv.y = acc[mt][nt][3];
                *(float2*)(P + (size_t)(mlo + 8) * N + nn) = vv;
            }
        }
    }
}

// ---------------- FC2 GEMM: 128x256 tile, 3-term fp16 split ------------------
#define F2_STAGE 49152

__global__ __launch_bounds__(256, 1) void gemm_fc2(
    const __half* __restrict__ Ahi, const __half* __restrict__ Alo,
    const __half* __restrict__ Bhi, const __half* __restrict__ Blo,
    float* __restrict__ Pf, int M, int N, int K, int kLen) {
    constexpr uint32_t ST_AH = 0, ST_AL = 8192, ST_BH = 16384, ST_BL = 32768;
    extern __shared__ char dynsmem[];
    uint32_t sb0 = smem_u32(dynsmem);

    int tid = threadIdx.x;
    int lane = tid & 31, wid = tid >> 5;
    int wm = wid >> 2, wn = wid & 3;
    int m0 = blockIdx.y * 128, n0 = blockIdx.x * 256;
    int kBase = blockIdx.z * kLen;

    int arow_l = tid >> 1;
    int lc = (tid & 1) * 2;
    int arow = min(m0 + arow_l, M - 1);
    const char* gAh = (const char*)(Ahi + (size_t)arow * K + kBase);
    const char* gAl = (const char*)(Alo + (size_t)arow * K + kBase);
    const char* gBh = (const char*)(Bhi + (size_t)(n0 + tid) * K + kBase);
    const char* gBl = (const char*)(Blo + (size_t)(n0 + tid) * K + kBase);
    uint32_t soA0 = sw64((uint32_t)(arow_l * 64 + lc * 16));
    uint32_t soA1 = sw64((uint32_t)(arow_l * 64 + (lc + 1) * 16));
    uint32_t soB[4];
    #pragma unroll
    for (int c = 0; c < 4; c++) soB[c] = sw64((uint32_t)(tid * 64 + c * 16));

    int nk = kLen >> 5;

    auto load_stage = [&](int j) {
        uint32_t sb = sb0 + (uint32_t)(j % NSTAGE) * F2_STAGE;
        int gbA = (j << 6) + (lc << 4);
        int gbB = (j << 6);
        cp16(sb + ST_AH + soA0, gAh + gbA);
        cp16(sb + ST_AH + soA1, gAh + gbA + 16);
        cp16(sb + ST_AL + soA0, gAl + gbA);
        cp16(sb + ST_AL + soA1, gAl + gbA + 16);
        #pragma unroll
        for (int c = 0; c < 4; c++) {
            cp16(sb + ST_BH + soB[c], gBh + gbB + c * 16);
            cp16(sb + ST_BL + soB[c], gBl + gbB + c * 16);
        }
        asm volatile("cp.async.commit_group;\n" ::);
    };

    int half = lane >> 4;
    int lr = lane & 15;
    uint32_t offA[4][2], offB[4][2];
    #pragma unroll
    for (int mt = 0; mt < 4; mt++)
        #pragma unroll
        for (int s = 0; s < 2; s++)
            offA[mt][s] = sw64((uint32_t)((wm * 64 + mt * 16 + lr) * 64 + (s * 2 + half) * 16));
    #pragma unroll
    for (int pr = 0; pr < 4; pr++)
        #pragma unroll
        for (int s = 0; s < 2; s++)
            offB[pr][s] = sw64((uint32_t)((wn * 64 + pr * 16 + lr) * 64 + (s * 2 + half) * 16));

    float acc[4][8][4];
    #pragma unroll
    for (int a = 0; a < 4; a++)
        #pragma unroll
        for (int b = 0; b < 8; b++)
            #pragma unroll
            for (int c = 0; c < 4; c++) acc[a][b][c] = 0.f;

    load_stage(0);
    load_stage(1);

    for (int i = 0; i < nk; i++) {
        if (i + 1 < nk) asm volatile("cp.async.wait_group 1;\n" ::);
        else            asm volatile("cp.async.wait_group 0;\n" ::);
        __syncthreads();
        if (i + 2 < nk) load_stage(i + 2);

        uint32_t sb = sb0 + (uint32_t)(i % NSTAGE) * F2_STAGE;
        #pragma unroll
        for (int s = 0; s < 2; s++) {
            uint32_t ah[4][4], al[4][4];
            uint32_t bh[8][2], bl[8][2];
            #pragma unroll
            for (int mt = 0; mt < 4; mt++) {
                ldm_x4(ah[mt], sb + ST_AH + offA[mt][s]);
                ldm_x4(al[mt], sb + ST_AL + offA[mt][s]);
            }
            #pragma unroll
            for (int pr = 0; pr < 4; pr++) {
                uint32_t t4[4];
                ldm_x4(t4, sb + ST_BH + offB[pr][s]);
                bh[pr * 2][0] = t4[0]; bh[pr * 2][1] = t4[2];
                bh[pr * 2 + 1][0] = t4[1]; bh[pr * 2 + 1][1] = t4[3];
                ldm_x4(t4, sb + ST_BL + offB[pr][s]);
                bl[pr * 2][0] = t4[0]; bl[pr * 2][1] = t4[2];
                bl[pr * 2 + 1][0] = t4[1]; bl[pr * 2 + 1][1] = t4[3];
            }
            #pragma unroll
            for (int mt = 0; mt < 4; mt++)
                #pragma unroll
                for (int nt = 0; nt < 8; nt++) {
                    mma16816(acc[mt][nt], ah[mt], bh[nt][0], bh[nt][1]);
                    mma16816(acc[mt][nt], al[mt], bh[nt][0], bh[nt][1]);
                    mma16816(acc[mt][nt], ah[mt], bl[nt][0], bl[nt][1]);
                }
        }
    }

    float* P = Pf + (size_t)blockIdx.z * M * N;
    int qr = lane >> 2, qc = (lane & 3) * 2;
    #pragma unroll
    for (int mt = 0; mt < 4; mt++) {
        int mlo = m0 + wm * 64 + mt * 16 + qr;
        #pragma unroll
        for (int nt = 0; nt < 8; nt++) {
            int nn = n0 + wn * 64 + nt * 8 + qc;
            if (mlo < M) {
                float2 vv; vv.x = acc[mt][nt][0]; vv.y = acc[mt][nt][1];
                *(float2*)(P + (size_t)mlo * N + nn) = vv;
            }
            if (mlo + 8 < M) {
                float2 vv; vv.x = acc[mt][nt][2]; vv.y = acc[mt][nt][3];
                *(float2*)(P + (size_t)(mlo + 8) * N + nn) = vv;
            }
        }
    }
}

// ---------------- FC1 reduce: sum partials + bias + relu -> x1 hi/lo ---------
__global__ __launch_bounds__(256) void reduce_fc1(
    const float* __restrict__ P, const float* __restrict__ bias,
    __half* __restrict__ Chi, __half* __restrict__ Clo, int MN, int N) {
    int i = blockIdx.x * 256 + threadIdx.x;
    if (i >= MN) return;
    float v = __ldg(bias + (i % N));
    #pragma unroll
    for (int z = 0; z < SPLITK; z++) v += P[(size_t)z * MN + i];
    v = fmaxf(v, 0.f);
    __half h = __float2half_rn(v);
    Chi[i] = h;
    Clo[i] = __float2half_rn(v - __half2float(h));
}

// ---------------- heads (fused FC2 reduce) -----------------------------------
__global__ __launch_bounds__(448) void heads_kernel(
    const float* __restrict__ P2, const float* __restrict__ b2,
    const float* __restrict__ wb, const float* __restrict__ bb,
    const float* __restrict__ wc, const float* __restrict__ bc,
    const float* __restrict__ wr, const float* __restrict__ br,
    const float* __restrict__ wu, const float* __restrict__ bu,
    float* __restrict__ out) {
    __shared__ float xs[DDIM];
    int n = blockIdx.x;
    const int MN = NROIS * DDIM;
    for (int i = threadIdx.x; i < DDIM; i += blockDim.x) {
        float v = __ldg(b2 + i);
        #pragma unroll
        for (int z = 0; z < SPLITK; z++) v += P2[(size_t)z * MN + n * DDIM + i];
        xs[i] = fmaxf(v, 0.f);
    }
    __syncthreads();
    int wid = threadIdx.x >> 5, lane = threadIdx.x & 31;
    const float* wrow;
    float bv;
    if (wid < 8)       { wrow = wb + wid * DDIM;        bv = bb[wid]; }
    else if (wid < 10) { wrow = wc + (wid - 8) * DDIM;  bv = bc[wid - 8]; }
    else if (wid < 12) { wrow = wr + (wid - 10) * DDIM; bv = br[wid - 10]; }
    else               { wrow = wu + (wid - 12) * DDIM; bv = bu[wid - 12]; }
    float s = 0.f;
    for (int i = lane; i < DDIM; i += 32) s += xs[i] * wrow[i];
    #pragma unroll
    for (int o = 16; o; o >>= 1) s += __shfl_down_sync(0xffffffff, s, o);
    if (lane == 0) {
        float v = s + bv;
        if (wid < 8)       out[n * 8 + wid] = v;
        else if (wid < 10) out[8000 + n * 2 + (wid - 8)] = v;
        else if (wid < 12) out[10000 + n * 4 + (wid - 10) * 2 + 0] = v;
        else               out[10000 + n * 4 + (wid - 12) * 2 + 1] = v;
    }
}

// ---------------- host launcher ---------------------------------------------
extern "C" void kernel_launch(void* const* d_in, const int* in_sizes, int n_in,
                              void* d_out, int out_size) {
    const float* fmap0 = (const float*)d_in[0];
    const float* fmap1 = (const float*)d_in[1];
    const float* fmap2 = (const float*)d_in[2];
    const float* fmap3 = (const float*)d_in[3];
    const float* rois  = (const float*)d_in[4];
    const float* w1    = (const float*)d_in[5];
    const float* b1    = (const float*)d_in[6];
    const float* w2    = (const float*)d_in[7];
    const float* b2    = (const float*)d_in[8];
    const float* wbbox = (const float*)d_in[9];
    const float* bbbox = (const float*)d_in[10];
    const float* wcls  = (const float*)d_in[11];
    const float* bcls  = (const float*)d_in[12];
    const float* wreg  = (const float*)d_in[13];
    const float* breg  = (const float*)d_in[14];
    const float* wunc  = (const float*)d_in[15];
    const float* bunc  = (const float*)d_in[16];
    float* out = (float*)d_out;

    __half* fT0;  cudaGetSymbolAddress((void**)&fT0, g_fT0);
    __half* fT1;  cudaGetSymbolAddress((void**)&fT1, g_fT1);
    __half* fT2;  cudaGetSymbolAddress((void**)&fT2, g_fT2);
    __half* fT3;  cudaGetSymbolAddress((void**)&fT3, g_fT3);
    __half *ph, *w1h, *w2h, *w2l, *x1h, *x1l;
    cudaGetSymbolAddress((void**)&ph,  g_ph);
    cudaGetSymbolAddress((void**)&w1h, g_w1h);
    cudaGetSymbolAddress((void**)&w2h, g_w2h);
    cudaGetSymbolAddress((void**)&w2l, g_w2l);
    cudaGetSymbolAddress((void**)&x1h, g_x1h);
    cudaGetSymbolAddress((void**)&x1l, g_x1l);
    float* part; cudaGetSymbolAddress((void**)&part, g_part);

    cudaFuncSetAttribute(gemm_fc1, cudaFuncAttributeMaxDynamicSharedMemorySize, NSTAGE * F1_STAGE);
    cudaFuncSetAttribute(gemm_fc2, cudaFuncAttributeMaxDynamicSharedMemorySize, NSTAGE * F2_STAGE);

    // weight prep: w1 -> single fp16, w2 -> fp16 hi/lo
    {
        int n1 = DDIM * K1 / 2;
        round_half_kernel<<<(n1 + 255) / 256, 256>>>(w1, w1h, n1);
        int n2 = DDIM * DDIM / 2;
        split_kernel<<<(n2 + 255) / 256, 256>>>(w2, w2h, w2l, n2);
    }

    dim3 tb(32, 8);
    transpose_nchw_nhwc<<<dim3(4, 6, NBATCH * 128), tb>>>(fmap0, fT0, 128, 128);
    transpose_nchw_nhwc<<<dim3(2, 6, NBATCH * 64),  tb>>>(fmap1, fT1, 64, 64);
    transpose_nchw_nhwc<<<dim3(1, 6, NBATCH * 32),  tb>>>(fmap2, fT2, 32, 32);
    transpose_nchw_nhwc<<<dim3(1, 6, NBATCH * 16),  tb>>>(fmap3, fT3, 16, 16);

    roialign_kernel<<<NROIS, 192>>>(rois);

    const int MN = NROIS * DDIM;
    // FC1: single-term fp16, 128x128 tile, 2 CTAs/SM, split-K=6 (288 CTAs)
    gemm_fc1<<<dim3(DDIM / 128, (NROIS + 127) / 128, SPLITK), 256, NSTAGE * F1_STAGE>>>(
        ph, w1h, part, NROIS, DDIM, K1, K1 / SPLITK);
    reduce_fc1<<<(MN + 255) / 256, 256>>>(part, b1, x1h, x1l, MN, DDIM);

    // FC2: 3-term fp16 split, 128x256 tile, split-K=6 (144 CTAs)
    gemm_fc2<<<dim3(DDIM / 256, (NROIS + 127) / 128, SPLITK), 256, NSTAGE * F2_STAGE>>>(
        x1h, x1l, w2h, w2l, part, NROIS, DDIM, DDIM, DDIM / SPLITK);

    // heads with fused FC2 reduce
    heads_kernel<<<NROIS, 448>>>(part, b2, wbbox, bbbox, wcls, bcls, wreg, breg,
                                 wunc, bunc, out);
}

// round 16
// speedup vs baseline: 1.2597x; 1.0661x over previous
#include <cuda_runtime.h>
#include <cuda_fp16.h>
#include <math.h>
#include <stdint.h>

#define NC    192
#define POOLS 7
#define NPTS  196
#define NROIS 1000
#define NBATCH 4
#define DDIM  768
#define K1    9408
#define SPLITK 6

// ---------------- scratch (device globals; no runtime allocation) -----------
__device__ __half g_fT0[NBATCH * 128 * 128 * NC];   // NHWC fp16 level 0
__device__ __half g_fT1[NBATCH * 64 * 64 * NC];
__device__ __half g_fT2[NBATCH * 32 * 32 * NC];
__device__ __half g_fT3[NBATCH * 16 * 16 * NC];
__device__ __half g_ph[(size_t)NROIS * K1];   // pooled (fp16, single)
__device__ __half g_w1h[(size_t)DDIM * K1];   // w1 single fp16
__device__ __half g_w2h[DDIM * DDIM];
__device__ __half g_w2l[DDIM * DDIM];
__device__ __half g_x1h[NROIS * DDIM];
__device__ __half g_x1l[NROIS * DDIM];
__device__ float g_part[(size_t)SPLITK * NROIS * DDIM];   // split-K partials

// ---------------- helpers ----------------------------------------------------
__device__ __forceinline__ uint32_t smem_u32(const void* p) {
    uint32_t a;
    asm("{ .reg .u64 t; cvta.to.shared.u64 t, %1; cvt.u32.u64 %0, t; }"
        : "=r"(a) : "l"(p));
    return a;
}
__device__ __forceinline__ void cp16(uint32_t s, const void* g) {
    asm volatile("cp.async.cg.shared.global [%0], [%1], 16;\n" :: "r"(s), "l"(g));
}
__device__ __forceinline__ uint32_t sw64(uint32_t o) { return o ^ ((o >> 3) & 0x30); }

__device__ __forceinline__ void ldm_x4(uint32_t* r, uint32_t addr) {
    asm volatile("ldmatrix.sync.aligned.m8n8.x4.shared.b16 {%0,%1,%2,%3}, [%4];"
                 : "=r"(r[0]), "=r"(r[1]), "=r"(r[2]), "=r"(r[3]) : "r"(addr));
}
__device__ __forceinline__ void mma16816(float* d, const uint32_t* a,
                                         const uint32_t b0, const uint32_t b1) {
    asm volatile(
        "mma.sync.aligned.m16n8k16.row.col.f32.f16.f16.f32 "
        "{%0,%1,%2,%3}, {%4,%5,%6,%7}, {%8,%9}, {%0,%1,%2,%3};"
        : "+f"(d[0]), "+f"(d[1]), "+f"(d[2]), "+f"(d[3])
        : "r"(a[0]), "r"(a[1]), "r"(a[2]), "r"(a[3]), "r"(b0), "r"(b1));
}

// ---------------- NCHW fp32 -> NHWC fp16 transpose ---------------------------
__global__ __launch_bounds__(256) void transpose_nchw_nhwc(
    const float* __restrict__ in, __half* __restrict__ out, int H, int W) {
    __shared__ float tile[32][33];
    int by = blockIdx.z;
    int b = by / H, y = by % H;
    int c0 = blockIdx.y * 32;
    int x0 = blockIdx.x * 32;
    const float* inp = in + ((size_t)b * NC) * H * W + (size_t)y * W;
    for (int i = threadIdx.y; i < 32; i += 8) {
        int c = c0 + i, x = x0 + threadIdx.x;
        float v = 0.f;
        if (c < NC && x < W) v = inp[(size_t)c * H * W + x];
        tile[i][threadIdx.x] = v;
    }
    __syncthreads();
    __half* outp = out + ((size_t)(b * H + y) * W) * NC;
    for (int i = threadIdx.y; i < 32; i += 8) {
        int x = x0 + i, c = c0 + threadIdx.x;
        if (c < NC && x < W) outp[(size_t)x * NC + c] = __float2half_rn(tile[threadIdx.x][i]);
    }
}

// ---------------- fp32 -> fp16 single round (x2 vectorized) -----------------
__global__ __launch_bounds__(256) void round_half_kernel(
    const float* __restrict__ in, __half* __restrict__ hi, int n2) {
    int i = blockIdx.x * 256 + threadIdx.x;
    if (i < n2) {
        float2 v = ((const float2*)in)[i];
        __half2 hh; hh.x = __float2half_rn(v.x); hh.y = __float2half_rn(v.y);
        ((__half2*)hi)[i] = hh;
    }
}

// ---------------- fp32 -> (fp16 hi, fp16 lo) split (x2 vectorized) ----------
__global__ __launch_bounds__(256) void split_kernel(
    const float* __restrict__ in, __half* __restrict__ hi,
    __half* __restrict__ lo, int n2) {
    int i = blockIdx.x * 256 + threadIdx.x;
    if (i < n2) {
        float2 v = ((const float2*)in)[i];
        __half h0 = __float2half_rn(v.x);
        __half h1 = __float2half_rn(v.y);
        __half2 hh; hh.x = h0; hh.y = h1;
        __half2 ll;
        ll.x = __float2half_rn(v.x - __half2float(h0));
        ll.y = __float2half_rn(v.y - __half2float(h1));
        ((__half2*)hi)[i] = hh;
        ((__half2*)lo)[i] = ll;
    }
}

// ---------------- RoIAlign (fp16 NHWC, 4-channel quads, 8B gathers) ----------
// 192 threads = 48 channel-quads x 4 bin-quarters (12/12/12/13 bins).
__global__ __launch_bounds__(192) void roialign_kernel(const float* __restrict__ rois) {
    __shared__ int   s_off[NPTS][4];
    __shared__ float s_w[NPTS][4];
    __shared__ float s_out[K1];

    int n = blockIdx.x;
    float ry1 = rois[n * 5 + 0], rx1 = rois[n * 5 + 1];
    float ry2 = rois[n * 5 + 2], rx2 = rois[n * 5 + 3];
    int bix = (int)rois[n * 5 + 4];

    float h = ry2 - ry1, w = rx2 - rx1;
    float lvlf = rintf(4.0f + 0.5f * log2f(h * w));
    int lvl = min(max((int)lvlf, 0), 3);

    int H, W;
    const __half* fm;
    if (lvl == 0)      { H = 128; W = 128; fm = g_fT0; }
    else if (lvl == 1) { H = 64;  W = 64;  fm = g_fT1; }
    else if (lvl == 2) { H = 32;  W = 32;  fm = g_fT2; }
    else               { H = 16;  W = 16;  fm = g_fT3; }
    const uint2* fm4 = (const uint2*)fm;   // 4 halves per element

    float Y1 = ry1 * H, X1 = rx1 * W, Y2 = ry2 * H, X2 = rx2 * W;
    float bin_h = fmaxf(Y2 - Y1, 1.0f) * (1.0f / POOLS);
    float bin_w = fmaxf(X2 - X1, 1.0f) * (1.0f / POOLS);

    for (int p = threadIdx.x; p < NPTS; p += blockDim.x) {
        int gy = p / 14, gx = p % 14;
        float grid_y = (float)(gy >> 1) + ((float)(gy & 1) + 0.5f) * 0.5f;
        float grid_x = (float)(gx >> 1) + ((float)(gx & 1) + 0.5f) * 0.5f;
        float y = Y1 + grid_y * bin_h;
        float x = X1 + grid_x * bin_w;
        bool valid = (y >= -1.0f) && (y <= (float)H) && (x >= -1.0f) && (x <= (float)W);
        y = fminf(fmaxf(y, 0.f), (float)(H - 1));
        x = fminf(fmaxf(x, 0.f), (float)(W - 1));
        int y0 = (int)floorf(y);
        int x0 = (int)floorf(x);
        int y1i = min(y0 + 1, H - 1);
        int x1i = min(x0 + 1, W - 1);
        float ly = y - (float)y0, lx = x - (float)x0;
        float vmul = valid ? 0.25f : 0.0f;
        int rowb = bix * H;
        // offsets in quad (8-byte) units: 48 quads per pixel
        s_off[p][0] = ((rowb + y0)  * W + x0)  * (NC / 4);
        s_off[p][1] = ((rowb + y0)  * W + x1i) * (NC / 4);
        s_off[p][2] = ((rowb + y1i) * W + x0)  * (NC / 4);
        s_off[p][3] = ((rowb + y1i) * W + x1i) * (NC / 4);
        s_w[p][0] = (1.f - ly) * (1.f - lx) * vmul;
        s_w[p][1] = (1.f - ly) * lx * vmul;
        s_w[p][2] = ly * (1.f - lx) * vmul;
        s_w[p][3] = ly * lx * vmul;
    }
    __syncthreads();

    int cq = threadIdx.x % 48;          // channel quad
    int part = threadIdx.x / 48;        // 0..3
    int bin0 = part * 12;
    int bin1 = bin0 + 12 + (part == 3 ? 1 : 0);   // 12,12,12,13 -> 49
    int c0 = cq * 4;
    for (int bin = bin0; bin < bin1; bin++) {
        int by = bin / POOLS, bx = bin % POOLS;
        float a0 = 0.f, a1 = 0.f, a2 = 0.f, a3 = 0.f;
        #pragma unroll
        for (int sy = 0; sy < 2; sy++) {
            #pragma unroll
            for (int sx = 0; sx < 2; sx++) {
                int p = (by * 2 + sy) * 14 + (bx * 2 + sx);
                #pragma unroll
                for (int q = 0; q < 4; q++) {
                    uint2 v = fm4[s_off[p][q] + cq];
                    float2 f01 = __half22float2(*reinterpret_cast<__half2*>(&v.x));
                    float2 f23 = __half22float2(*reinterpret_cast<__half2*>(&v.y));
                    float wq = s_w[p][q];
                    a0 += wq * f01.x;
                    a1 += wq * f01.y;
                    a2 += wq * f23.x;
                    a3 += wq * f23.y;
                }
            }
        }
        s_out[(c0 + 0) * 49 + bin] = a0;
        s_out[(c0 + 1) * 49 + bin] = a1;
        s_out[(c0 + 2) * 49 + bin] = a2;
        s_out[(c0 + 3) * 49 + bin] = a3;
    }
    __syncthreads();
    __half* dh = g_ph + (size_t)n * K1;
    for (int i = threadIdx.x; i < K1; i += blockDim.x) {
        dh[i] = __float2half_rn(s_out[i]);
    }
}

// ---------------- FC1 GEMM: 128x128 tile, 2 CTAs/SM, single fp16, 4 stages ---
#define F1_NSTAGE 4
#define F1_STAGE 16384   // A 8KB + B 8KB

__global__ __launch_bounds__(256, 2) void gemm_fc1(
    const __half* __restrict__ A, const __half* __restrict__ B,
    float* __restrict__ Pf, int M, int N, int K, int kLen) {
    extern __shared__ char dynsmem[];
    uint32_t sb0 = smem_u32(dynsmem);

    int tid = threadIdx.x;
    int lane = tid & 31, wid = tid >> 5;
    int wm = wid >> 1, wn = wid & 1;     // 4 x 2 warp grid, warp tile 32x64
    int m0 = blockIdx.y * 128, n0 = blockIdx.x * 128;
    int kBase = blockIdx.z * kLen;

    int lrow = tid >> 1;
    int lc = (tid & 1) * 2;
    int arow = min(m0 + lrow, M - 1);
    const char* gA = (const char*)(A + (size_t)arow * K + kBase);
    const char* gB = (const char*)(B + (size_t)(n0 + lrow) * K + kBase);
    uint32_t so0 = sw64((uint32_t)(lrow * 64 + lc * 16));
    uint32_t so1 = sw64((uint32_t)(lrow * 64 + (lc + 1) * 16));

    int nk = kLen >> 5;

    auto load_stage = [&](int j) {
        uint32_t sb = sb0 + (uint32_t)(j % F1_NSTAGE) * F1_STAGE;
        int gb = (j << 6) + (lc << 4);
        cp16(sb + so0, gA + gb);
        cp16(sb + so1, gA + gb + 16);
        cp16(sb + 8192 + so0, gB + gb);
        cp16(sb + 8192 + so1, gB + gb + 16);
        asm volatile("cp.async.commit_group;\n" ::);
    };

    int half = lane >> 4;
    int lr = lane & 15;
    uint32_t offA[2][2], offB[4][2];
    #pragma unroll
    for (int mt = 0; mt < 2; mt++)
        #pragma unroll
        for (int s = 0; s < 2; s++)
            offA[mt][s] = sw64((uint32_t)((wm * 32 + mt * 16 + lr) * 64 + (s * 2 + half) * 16));
    #pragma unroll
    for (int pr = 0; pr < 4; pr++)
        #pragma unroll
        for (int s = 0; s < 2; s++)
            offB[pr][s] = sw64((uint32_t)((wn * 64 + pr * 16 + lr) * 64 + (s * 2 + half) * 16));

    float acc[2][8][4];
    #pragma unroll
    for (int a = 0; a < 2; a++)
        #pragma unroll
        for (int b = 0; b < 8; b++)
            #pragma unroll
            for (int c = 0; c < 4; c++) acc[a][b][c] = 0.f;

    load_stage(0);
    load_stage(1);
    load_stage(2);

    for (int i = 0; i < nk; i++) {
        int rem = nk - 1 - i;
        if (rem >= 2)      asm volatile("cp.async.wait_group 2;\n" ::);
        else if (rem == 1) asm volatile("cp.async.wait_group 1;\n" ::);
        else               asm volatile("cp.async.wait_group 0;\n" ::);
        __syncthreads();
        if (i + 3 < nk) load_stage(i + 3);

        uint32_t sb = sb0 + (uint32_t)(i % F1_NSTAGE) * F1_STAGE;
        #pragma unroll
        for (int s = 0; s < 2; s++) {
            uint32_t ah[2][4], bh[8][2];
            #pragma unroll
            for (int mt = 0; mt < 2; mt++)
                ldm_x4(ah[mt], sb + offA[mt][s]);
            #pragma unroll
            for (int pr = 0; pr < 4; pr++) {
                uint32_t t4[4];
                ldm_x4(t4, sb + 8192 + offB[pr][s]);
                bh[pr * 2][0] = t4[0]; bh[pr * 2][1] = t4[2];
                bh[pr * 2 + 1][0] = t4[1]; bh[pr * 2 + 1][1] = t4[3];
            }
            #pragma unroll
            for (int mt = 0; mt < 2; mt++)
                #pragma unroll
                for (int nt = 0; nt < 8; nt++)
                    mma16816(acc[mt][nt], ah[mt], bh[nt][0], bh[nt][1]);
        }
    }

    float* P = Pf + (size_t)blockIdx.z * M * N;
    int qr = lane >> 2, qc = (lane & 3) * 2;
    #pragma unroll
    for (int mt = 0; mt < 2; mt++) {
        int mlo = m0 + wm * 32 + mt * 16 + qr;
        #pragma unroll
        for (int nt = 0; nt < 8; nt++) {
            int nn = n0 + wn * 64 + nt * 8 + qc;
            if (mlo < M) {
                float2 vv; vv.x = acc[mt][nt][0]; vv.y = acc[mt][nt][1];
                *(float2*)(P + (size_t)mlo * N + nn) = vv;
            }
            if (mlo + 8 < M) {
                float2 vv; vv.x = acc[mt][nt][2]; vv.y = acc[mt][nt][3];
                *(float2*)(P + (size_t)(mlo + 8) * N + nn) = vv;
            }
        }
    }
}

// ---------------- FC2 GEMM: 128x256 tile, 3-term fp16 split ------------------
#define NSTAGE 3
#define F2_STAGE 49152

__global__ __launch_bounds__(256, 1) void gemm_fc2(
    const __half* __restrict__ Ahi, const __half* __restrict__ Alo,
    const __half* __restrict__ Bhi, const __half* __restrict__ Blo,
    float* __restrict__ Pf, int M, int N, int K, int kLen) {
    constexpr uint32_t ST_AH = 0, ST_AL = 8192, ST_BH = 16384, ST_BL = 32768;
    extern __shared__ char dynsmem[];
    uint32_t sb0 = smem_u32(dynsmem);

    int tid = threadIdx.x;
    int lane = tid & 31, wid = tid >> 5;
    int wm = wid >> 2, wn = wid & 3;
    int m0 = blockIdx.y * 128, n0 = blockIdx.x * 256;
    int kBase = blockIdx.z * kLen;

    int arow_l = tid >> 1;
    int lc = (tid & 1) * 2;
    int arow = min(m0 + arow_l, M - 1);
    const char* gAh = (const char*)(Ahi + (size_t)arow * K + kBase);
    const char* gAl = (const char*)(Alo + (size_t)arow * K + kBase);
    const char* gBh = (const char*)(Bhi + (size_t)(n0 + tid) * K + kBase);
    const char* gBl = (const char*)(Blo + (size_t)(n0 + tid) * K + kBase);
    uint32_t soA0 = sw64((uint32_t)(arow_l * 64 + lc * 16));
    uint32_t soA1 = sw64((uint32_t)(arow_l * 64 + (lc + 1) * 16));
    uint32_t soB[4];
    #pragma unroll
    for (int c = 0; c < 4; c++) soB[c] = sw64((uint32_t)(tid * 64 + c * 16));

    int nk = kLen >> 5;

    auto load_stage = [&](int j) {
        uint32_t sb = sb0 + (uint32_t)(j % NSTAGE) * F2_STAGE;
        int gbA = (j << 6) + (lc << 4);
        int gbB = (j << 6);
        cp16(sb + ST_AH + soA0, gAh + gbA);
        cp16(sb + ST_AH + soA1, gAh + gbA + 16);
        cp16(sb + ST_AL + soA0, gAl + gbA);
        cp16(sb + ST_AL + soA1, gAl + gbA + 16);
        #pragma unroll
        for (int c = 0; c < 4; c++) {
            cp16(sb + ST_BH + soB[c], gBh + gbB + c * 16);
            cp16(sb + ST_BL + soB[c], gBl + gbB + c * 16);
        }
        asm volatile("cp.async.commit_group;\n" ::);
    };

    int half = lane >> 4;
    int lr = lane & 15;
    uint32_t offA[4][2], offB[4][2];
    #pragma unroll
    for (int mt = 0; mt < 4; mt++)
        #pragma unroll
        for (int s = 0; s < 2; s++)
            offA[mt][s] = sw64((uint32_t)((wm * 64 + mt * 16 + lr) * 64 + (s * 2 + half) * 16));
    #pragma unroll
    for (int pr = 0; pr < 4; pr++)
        #pragma unroll
        for (int s = 0; s < 2; s++)
            offB[pr][s] = sw64((uint32_t)((wn * 64 + pr * 16 + lr) * 64 + (s * 2 + half) * 16));

    float acc[4][8][4];
    #pragma unroll
    for (int a = 0; a < 4; a++)
        #pragma unroll
        for (int b = 0; b < 8; b++)
            #pragma unroll
            for (int c = 0; c < 4; c++) acc[a][b][c] = 0.f;

    load_stage(0);
    load_stage(1);

    for (int i = 0; i < nk; i++) {
        if (i + 1 < nk) asm volatile("cp.async.wait_group 1;\n" ::);
        else            asm volatile("cp.async.wait_group 0;\n" ::);
        __syncthreads();
        if (i + 2 < nk) load_stage(i + 2);

        uint32_t sb = sb0 + (uint32_t)(i % NSTAGE) * F2_STAGE;
        #pragma unroll
        for (int s = 0; s < 2; s++) {
            uint32_t ah[4][4], al[4][4];
            uint32_t bh[8][2], bl[8][2];
            #pragma unroll
            for (int mt = 0; mt < 4; mt++) {
                ldm_x4(ah[mt], sb + ST_AH + offA[mt][s]);
                ldm_x4(al[mt], sb + ST_AL + offA[mt][s]);
            }
            #pragma unroll
            for (int pr = 0; pr < 4; pr++) {
                uint32_t t4[4];
                ldm_x4(t4, sb + ST_BH + offB[pr][s]);
                bh[pr * 2][0] = t4[0]; bh[pr * 2][1] = t4[2];
                bh[pr * 2 + 1][0] = t4[1]; bh[pr * 2 + 1][1] = t4[3];
                ldm_x4(t4, sb + ST_BL + offB[pr][s]);
                bl[pr * 2][0] = t4[0]; bl[pr * 2][1] = t4[2];
                bl[pr * 2 + 1][0] = t4[1]; bl[pr * 2 + 1][1] = t4[3];
            }
            #pragma unroll
            for (int mt = 0; mt < 4; mt++)
                #pragma unroll
                for (int nt = 0; nt < 8; nt++) {
                    mma16816(acc[mt][nt], ah[mt], bh[nt][0], bh[nt][1]);
                    mma16816(acc[mt][nt], al[mt], bh[nt][0], bh[nt][1]);
                    mma16816(acc[mt][nt], ah[mt], bl[nt][0], bl[nt][1]);
                }
        }
    }

    float* P = Pf + (size_t)blockIdx.z * M * N;
    int qr = lane >> 2, qc = (lane & 3) * 2;
    #pragma unroll
    for (int mt = 0; mt < 4; mt++) {
        int mlo = m0 + wm * 64 + mt * 16 + qr;
        #pragma unroll
        for (int nt = 0; nt < 8; nt++) {
            int nn = n0 + wn * 64 + nt * 8 + qc;
            if (mlo < M) {
                float2 vv; vv.x = acc[mt][nt][0]; vv.y = acc[mt][nt][1];
                *(float2*)(P + (size_t)mlo * N + nn) = vv;
            }
            if (mlo + 8 < M) {
                float2 vv; vv.x = acc[mt][nt][2]; vv.y = acc[mt][nt][3];
                *(float2*)(P + (size_t)(mlo + 8) * N + nn) = vv;
            }
        }
    }
}

// ---------------- FC1 reduce: sum partials + bias + relu -> x1 hi/lo ---------
__global__ __launch_bounds__(256) void reduce_fc1(
    const float* __restrict__ P, const float* __restrict__ bias,
    __half* __restrict__ Chi, __half* __restrict__ Clo, int MN, int N) {
    int i = blockIdx.x * 256 + threadIdx.x;
    if (i >= MN) return;
    float v = __ldg(bias + (i % N));
    #pragma unroll
    for (int z = 0; z < SPLITK; z++) v += P[(size_t)z * MN + i];
    v = fmaxf(v, 0.f);
    __half h = __float2half_rn(v);
    Chi[i] = h;
    Clo[i] = __float2half_rn(v - __half2float(h));
}

// ---------------- heads (fused FC2 reduce) -----------------------------------
__global__ __launch_bounds__(448) void heads_kernel(
    const float* __restrict__ P2, const float* __restrict__ b2,
    const float* __restrict__ wb, const float* __restrict__ bb,
    const float* __restrict__ wc, const float* __restrict__ bc,
    const float* __restrict__ wr, const float* __restrict__ br,
    const float* __restrict__ wu, const float* __restrict__ bu,
    float* __restrict__ out) {
    __shared__ float xs[DDIM];
    int n = blockIdx.x;
    const int MN = NROIS * DDIM;
    for (int i = threadIdx.x; i < DDIM; i += blockDim.x) {
        float v = __ldg(b2 + i);
        #pragma unroll
        for (int z = 0; z < SPLITK; z++) v += P2[(size_t)z * MN + n * DDIM + i];
        xs[i] = fmaxf(v, 0.f);
    }
    __syncthreads();
    int wid = threadIdx.x >> 5, lane = threadIdx.x & 31;
    const float* wrow;
    float bv;
    if (wid < 8)       { wrow = wb + wid * DDIM;        bv = bb[wid]; }
    else if (wid < 10) { wrow = wc + (wid - 8) * DDIM;  bv = bc[wid - 8]; }
    else if (wid < 12) { wrow = wr + (wid - 10) * DDIM; bv = br[wid - 10]; }
    else               { wrow = wu + (wid - 12) * DDIM; bv = bu[wid - 12]; }
    float s = 0.f;
    for (int i = lane; i < DDIM; i += 32) s += xs[i] * wrow[i];
    #pragma unroll
    for (int o = 16; o; o >>= 1) s += __shfl_down_sync(0xffffffff, s, o);
    if (lane == 0) {
        float v = s + bv;
        if (wid < 8)       out[n * 8 + wid] = v;
        else if (wid < 10) out[8000 + n * 2 + (wid - 8)] = v;
        else if (wid < 12) out[10000 + n * 4 + (wid - 10) * 2 + 0] = v;
        else               out[10000 + n * 4 + (wid - 12) * 2 + 1] = v;
    }
}

// ---------------- host launcher ---------------------------------------------
extern "C" void kernel_launch(void* const* d_in, const int* in_sizes, int n_in,
                              void* d_out, int out_size) {
    const float* fmap0 = (const float*)d_in[0];
    const float* fmap1 = (const float*)d_in[1];
    const float* fmap2 = (const float*)d_in[2];
    const float* fmap3 = (const float*)d_in[3];
    const float* rois  = (const float*)d_in[4];
    const float* w1    = (const float*)d_in[5];
    const float* b1    = (const float*)d_in[6];
    const float* w2    = (const float*)d_in[7];
    const float* b2    = (const float*)d_in[8];
    const float* wbbox = (const float*)d_in[9];
    const float* bbbox = (const float*)d_in[10];
    const float* wcls  = (const float*)d_in[11];
    const float* bcls  = (const float*)d_in[12];
    const float* wreg  = (const float*)d_in[13];
    const float* breg  = (const float*)d_in[14];
    const float* wunc  = (const float*)d_in[15];
    const float* bunc  = (const float*)d_in[16];
    float* out = (float*)d_out;

    __half* fT0;  cudaGetSymbolAddress((void**)&fT0, g_fT0);
    __half* fT1;  cudaGetSymbolAddress((void**)&fT1, g_fT1);
    __half* fT2;  cudaGetSymbolAddress((void**)&fT2, g_fT2);
    __half* fT3;  cudaGetSymbolAddress((void**)&fT3, g_fT3);
    __half *ph, *w1h, *w2h, *w2l, *x1h, *x1l;
    cudaGetSymbolAddress((void**)&ph,  g_ph);
    cudaGetSymbolAddress((void**)&w1h, g_w1h);
    cudaGetSymbolAddress((void**)&w2h, g_w2h);
    cudaGetSymbolAddress((void**)&w2l, g_w2l);
    cudaGetSymbolAddress((void**)&x1h, g_x1h);
    cudaGetSymbolAddress((void**)&x1l, g_x1l);
    float* part; cudaGetSymbolAddress((void**)&part, g_part);

    cudaFuncSetAttribute(gemm_fc1, cudaFuncAttributeMaxDynamicSharedMemorySize, F1_NSTAGE * F1_STAGE);
    cudaFuncSetAttribute(gemm_fc2, cudaFuncAttributeMaxDynamicSharedMemorySize, NSTAGE * F2_STAGE);

    // Lazy-created side stream + events (created on the uncaptured correctness
    // call; reused — not created — during graph capture).
    static cudaStream_t s1 = nullptr;
    static cudaEvent_t evFork = nullptr, evJoin = nullptr;
    if (s1 == nullptr) {
        cudaStreamCreateWithFlags(&s1, cudaStreamNonBlocking);
        cudaEventCreateWithFlags(&evFork, cudaEventDisableTiming);
        cudaEventCreateWithFlags(&evJoin, cudaEventDisableTiming);
    }

    // Fork: weight prep on s1, concurrent with transposes + RoIAlign on main.
    cudaEventRecord(evFork, 0);
    cudaStreamWaitEvent(s1, evFork, 0);
    {
        int n1 = DDIM * K1 / 2;
        round_half_kernel<<<(n1 + 255) / 256, 256, 0, s1>>>(w1, w1h, n1);
        int n2 = DDIM * DDIM / 2;
        split_kernel<<<(n2 + 255) / 256, 256, 0, s1>>>(w2, w2h, w2l, n2);
    }
    cudaEventRecord(evJoin, s1);

    dim3 tb(32, 8);
    transpose_nchw_nhwc<<<dim3(4, 6, NBATCH * 128), tb>>>(fmap0, fT0, 128, 128);
    transpose_nchw_nhwc<<<dim3(2, 6, NBATCH * 64),  tb>>>(fmap1, fT1, 64, 64);
    transpose_nchw_nhwc<<<dim3(1, 6, NBATCH * 32),  tb>>>(fmap2, fT2, 32, 32);
    transpose_nchw_nhwc<<<dim3(1, 6, NBATCH * 16),  tb>>>(fmap3, fT3, 16, 16);

    roialign_kernel<<<NROIS, 192>>>(rois);

    // Join before FC1 (needs w1h).
    cudaStreamWaitEvent(0, evJoin, 0);

    const int MN = NROIS * DDIM;
    // FC1: single-term fp16, 128x128 tile, 2 CTAs/SM, 4-stage, split-K=6
    gemm_fc1<<<dim3(DDIM / 128, (NROIS + 127) / 128, SPLITK), 256, F1_NSTAGE * F1_STAGE>>>(
        ph, w1h, part, NROIS, DDIM, K1, K1 / SPLITK);
    reduce_fc1<<<(MN + 255) / 256, 256>>>(part, b1, x1h, x1l, MN, DDIM);

    // FC2: 3-term fp16 split, 128x256 tile, split-K=6
    gemm_fc2<<<dim3(DDIM / 256, (NROIS + 127) / 128, SPLITK), 256, NSTAGE * F2_STAGE>>>(
        x1h, x1l, w2h, w2l, part, NROIS, DDIM, DDIM, DDIM / SPLITK);

    // heads with fused FC2 reduce
    heads_kernel<<<NROIS, 448>>>(part, b2, wbbox, bbbox, wcls, bcls, wreg, breg,
                                 wunc, bunc, out);
}

// round 17
// speedup vs baseline: 1.3369x; 1.0613x over previous
#include <cuda_runtime.h>
#include <cuda_fp16.h>
#include <math.h>
#include <stdint.h>

#define NC    192
#define POOLS 7
#define NPTS  196
#define NROIS 1000
#define NBATCH 4
#define DDIM  768
#define K1    9408
#define SPLITK 6

// ---------------- scratch (device globals; no runtime allocation) -----------
__device__ __half g_fT0[NBATCH * 128 * 128 * NC];   // NHWC fp16 level 0
__device__ __half g_fT1[NBATCH * 64 * 64 * NC];
__device__ __half g_fT2[NBATCH * 32 * 32 * NC];
__device__ __half g_fT3[NBATCH * 16 * 16 * NC];
__device__ __half g_ph[(size_t)NROIS * K1];   // pooled (fp16, single)
__device__ __half g_w1h[(size_t)DDIM * K1];   // w1 single fp16
__device__ __half g_w2h[DDIM * DDIM];
__device__ __half g_w2l[DDIM * DDIM];
__device__ __half g_x1h[NROIS * DDIM];
__device__ __half g_x1l[NROIS * DDIM];
__device__ float g_part[(size_t)SPLITK * NROIS * DDIM];   // split-K partials

// ---------------- helpers ----------------------------------------------------
__device__ __forceinline__ uint32_t smem_u32(const void* p) {
    uint32_t a;
    asm("{ .reg .u64 t; cvta.to.shared.u64 t, %1; cvt.u32.u64 %0, t; }"
        : "=r"(a) : "l"(p));
    return a;
}
__device__ __forceinline__ void cp16(uint32_t s, const void* g) {
    asm volatile("cp.async.cg.shared.global [%0], [%1], 16;\n" :: "r"(s), "l"(g));
}
__device__ __forceinline__ uint32_t sw64(uint32_t o) { return o ^ ((o >> 3) & 0x30); }

__device__ __forceinline__ void ldm_x4(uint32_t* r, uint32_t addr) {
    asm volatile("ldmatrix.sync.aligned.m8n8.x4.shared.b16 {%0,%1,%2,%3}, [%4];"
                 : "=r"(r[0]), "=r"(r[1]), "=r"(r[2]), "=r"(r[3]) : "r"(addr));
}
__device__ __forceinline__ void mma16816(float* d, const uint32_t* a,
                                         const uint32_t b0, const uint32_t b1) {
    asm volatile(
        "mma.sync.aligned.m16n8k16.row.col.f32.f16.f16.f32 "
        "{%0,%1,%2,%3}, {%4,%5,%6,%7}, {%8,%9}, {%0,%1,%2,%3};"
        : "+f"(d[0]), "+f"(d[1]), "+f"(d[2]), "+f"(d[3])
        : "r"(a[0]), "r"(a[1]), "r"(a[2]), "r"(a[3]), "r"(b0), "r"(b1));
}

// ---------------- fused NCHW fp32 -> NHWC fp16 transpose (all 4 levels) ------
// Flat grid: L0 4x6x512=12288, L1 2x6x256=3072, L2 1x6x128=768, L3 1x6x64=384.
#define TP_TOTAL 16512
__global__ __launch_bounds__(256) void transpose_all(
    const float* __restrict__ f0, const float* __restrict__ f1,
    const float* __restrict__ f2, const float* __restrict__ f3) {
    __shared__ float tile[32][33];
    int id = blockIdx.x;
    const float* in;
    __half* outbase;
    int H, W, tilesX;
    if (id < 12288)      { in = f0; outbase = g_fT0; H = 128; W = 128; tilesX = 4; }
    else if (id < 15360) { id -= 12288; in = f1; outbase = g_fT1; H = 64; W = 64; tilesX = 2; }
    else if (id < 16128) { id -= 15360; in = f2; outbase = g_fT2; H = 32; W = 32; tilesX = 1; }
    else                 { id -= 16128; in = f3; outbase = g_fT3; H = 16; W = 16; tilesX = 1; }
    int bx = id % tilesX; id /= tilesX;
    int cy = id % 6;      id /= 6;
    int b = id / H, y = id % H;
    int c0 = cy * 32, x0 = bx * 32;

    const float* inp = in + ((size_t)b * NC) * H * W + (size_t)y * W;
    for (int i = threadIdx.y; i < 32; i += 8) {
        int c = c0 + i, x = x0 + threadIdx.x;
        float v = 0.f;
        if (c < NC && x < W) v = inp[(size_t)c * H * W + x];
        tile[i][threadIdx.x] = v;
    }
    __syncthreads();
    __half* outp = outbase + ((size_t)(b * H + y) * W) * NC;
    for (int i = threadIdx.y; i < 32; i += 8) {
        int x = x0 + i, c = c0 + threadIdx.x;
        if (c < NC && x < W) outp[(size_t)x * NC + c] = __float2half_rn(tile[threadIdx.x][i]);
    }
}

// ---------------- fp32 -> fp16 single round (x2 vectorized) -----------------
__global__ __launch_bounds__(256) void round_half_kernel(
    const float* __restrict__ in, __half* __restrict__ hi, int n2) {
    int i = blockIdx.x * 256 + threadIdx.x;
    if (i < n2) {
        float2 v = ((const float2*)in)[i];
        __half2 hh; hh.x = __float2half_rn(v.x); hh.y = __float2half_rn(v.y);
        ((__half2*)hi)[i] = hh;
    }
}

// ---------------- fp32 -> (fp16 hi, fp16 lo) split (x2 vectorized) ----------
__global__ __launch_bounds__(256) void split_kernel(
    const float* __restrict__ in, __half* __restrict__ hi,
    __half* __restrict__ lo, int n2) {
    int i = blockIdx.x * 256 + threadIdx.x;
    if (i < n2) {
        float2 v = ((const float2*)in)[i];
        __half h0 = __float2half_rn(v.x);
        __half h1 = __float2half_rn(v.y);
        __half2 hh; hh.x = h0; hh.y = h1;
        __half2 ll;
        ll.x = __float2half_rn(v.x - __half2float(h0));
        ll.y = __float2half_rn(v.y - __half2float(h1));
        ((__half2*)hi)[i] = hh;
        ((__half2*)lo)[i] = ll;
    }
}

// ---------------- RoIAlign (fp16 NHWC, 8-channel octs, 16B gathers) ----------
// 192 threads = 24 channel-octs x 8 bin-parts (7x6 + 1x7 = 49 bins).
__global__ __launch_bounds__(192) void roialign_kernel(const float* __restrict__ rois) {
    __shared__ int   s_off[NPTS][4];
    __shared__ float s_w[NPTS][4];
    __shared__ float s_out[K1];

    int n = blockIdx.x;
    float ry1 = rois[n * 5 + 0], rx1 = rois[n * 5 + 1];
    float ry2 = rois[n * 5 + 2], rx2 = rois[n * 5 + 3];
    int bix = (int)rois[n * 5 + 4];

    float h = ry2 - ry1, w = rx2 - rx1;
    float lvlf = rintf(4.0f + 0.5f * log2f(h * w));
    int lvl = min(max((int)lvlf, 0), 3);

    int H, W;
    const __half* fm;
    if (lvl == 0)      { H = 128; W = 128; fm = g_fT0; }
    else if (lvl == 1) { H = 64;  W = 64;  fm = g_fT1; }
    else if (lvl == 2) { H = 32;  W = 32;  fm = g_fT2; }
    else               { H = 16;  W = 16;  fm = g_fT3; }
    const uint4* fm8 = (const uint4*)fm;   // 8 halves per element

    float Y1 = ry1 * H, X1 = rx1 * W, Y2 = ry2 * H, X2 = rx2 * W;
    float bin_h = fmaxf(Y2 - Y1, 1.0f) * (1.0f / POOLS);
    float bin_w = fmaxf(X2 - X1, 1.0f) * (1.0f / POOLS);

    for (int p = threadIdx.x; p < NPTS; p += blockDim.x) {
        int gy = p / 14, gx = p % 14;
        float grid_y = (float)(gy >> 1) + ((float)(gy & 1) + 0.5f) * 0.5f;
        float grid_x = (float)(gx >> 1) + ((float)(gx & 1) + 0.5f) * 0.5f;
        float y = Y1 + grid_y * bin_h;
        float x = X1 + grid_x * bin_w;
        bool valid = (y >= -1.0f) && (y <= (float)H) && (x >= -1.0f) && (x <= (float)W);
        y = fminf(fmaxf(y, 0.f), (float)(H - 1));
        x = fminf(fmaxf(x, 0.f), (float)(W - 1));
        int y0 = (int)floorf(y);
        int x0 = (int)floorf(x);
        int y1i = min(y0 + 1, H - 1);
        int x1i = min(x0 + 1, W - 1);
        float ly = y - (float)y0, lx = x - (float)x0;
        float vmul = valid ? 0.25f : 0.0f;
        int rowb = bix * H;
        // offsets in oct (16-byte) units: 24 octs per pixel
        s_off[p][0] = ((rowb + y0)  * W + x0)  * (NC / 8);
        s_off[p][1] = ((rowb + y0)  * W + x1i) * (NC / 8);
        s_off[p][2] = ((rowb + y1i) * W + x0)  * (NC / 8);
        s_off[p][3] = ((rowb + y1i) * W + x1i) * (NC / 8);
        s_w[p][0] = (1.f - ly) * (1.f - lx) * vmul;
        s_w[p][1] = (1.f - ly) * lx * vmul;
        s_w[p][2] = ly * (1.f - lx) * vmul;
        s_w[p][3] = ly * lx * vmul;
    }
    __syncthreads();

    int co = threadIdx.x % 24;          // channel oct
    int part = threadIdx.x / 24;        // 0..7
    int bin0 = part * 6;
    int bin1 = bin0 + 6 + (part == 7 ? 1 : 0);   // 7x6 + 7 = 49
    int c0 = co * 8;
    for (int bin = bin0; bin < bin1; bin++) {
        int by = bin / POOLS, bx = bin % POOLS;
        float a[8];
        #pragma unroll
        for (int k = 0; k < 8; k++) a[k] = 0.f;
        #pragma unroll
        for (int sy = 0; sy < 2; sy++) {
            #pragma unroll
            for (int sx = 0; sx < 2; sx++) {
                int p = (by * 2 + sy) * 14 + (bx * 2 + sx);
                #pragma unroll
                for (int q = 0; q < 4; q++) {
                    uint4 v = fm8[s_off[p][q] + co];
                    float wq = s_w[p][q];
                    const __half2* hv = reinterpret_cast<const __half2*>(&v);
                    #pragma unroll
                    for (int k = 0; k < 4; k++) {
                        float2 f = __half22float2(hv[k]);
                        a[2 * k]     += wq * f.x;
                        a[2 * k + 1] += wq * f.y;
                    }
                }
            }
        }
        #pragma unroll
        for (int k = 0; k < 8; k++)
            s_out[(c0 + k) * 49 + bin] = a[k];
    }
    __syncthreads();
    __half* dh = g_ph + (size_t)n * K1;
    for (int i = threadIdx.x; i < K1; i += blockDim.x) {
        dh[i] = __float2half_rn(s_out[i]);
    }
}

// ---------------- FC1 GEMM: 128x128 tile, 2 CTAs/SM, single fp16, 4 stages ---
#define F1_NSTAGE 4
#define F1_STAGE 16384   // A 8KB + B 8KB

__global__ __launch_bounds__(256, 2) void gemm_fc1(
    const __half* __restrict__ A, const __half* __restrict__ B,
    float* __restrict__ Pf, int M, int N, int K, int kLen) {
    extern __shared__ char dynsmem[];
    uint32_t sb0 = smem_u32(dynsmem);

    int tid = threadIdx.x;
    int lane = tid & 31, wid = tid >> 5;
    int wm = wid >> 1, wn = wid & 1;     // 4 x 2 warp grid, warp tile 32x64
    int m0 = blockIdx.y * 128, n0 = blockIdx.x * 128;
    int kBase = blockIdx.z * kLen;

    int lrow = tid >> 1;
    int lc = (tid & 1) * 2;
    int arow = min(m0 + lrow, M - 1);
    const char* gA = (const char*)(A + (size_t)arow * K + kBase);
    const char* gB = (const char*)(B + (size_t)(n0 + lrow) * K + kBase);
    uint32_t so0 = sw64((uint32_t)(lrow * 64 + lc * 16));
    uint32_t so1 = sw64((uint32_t)(lrow * 64 + (lc + 1) * 16));

    int nk = kLen >> 5;

    auto load_stage = [&](int j) {
        uint32_t sb = sb0 + (uint32_t)(j % F1_NSTAGE) * F1_STAGE;
        int gb = (j << 6) + (lc << 4);
        cp16(sb + so0, gA + gb);
        cp16(sb + so1, gA + gb + 16);
        cp16(sb + 8192 + so0, gB + gb);
        cp16(sb + 8192 + so1, gB + gb + 16);
        asm volatile("cp.async.commit_group;\n" ::);
    };

    int half = lane >> 4;
    int lr = lane & 15;
    uint32_t offA[2][2], offB[4][2];
    #pragma unroll
    for (int mt = 0; mt < 2; mt++)
        #pragma unroll
        for (int s = 0; s < 2; s++)
            offA[mt][s] = sw64((uint32_t)((wm * 32 + mt * 16 + lr) * 64 + (s * 2 + half) * 16));
    #pragma unroll
    for (int pr = 0; pr < 4; pr++)
        #pragma unroll
        for (int s = 0; s < 2; s++)
            offB[pr][s] = sw64((uint32_t)((wn * 64 + pr * 16 + lr) * 64 + (s * 2 + half) * 16));

    float acc[2][8][4];
    #pragma unroll
    for (int a = 0; a < 2; a++)
        #pragma unroll
        for (int b = 0; b < 8; b++)
            #pragma unroll
            for (int c = 0; c < 4; c++) acc[a][b][c] = 0.f;

    load_stage(0);
    load_stage(1);
    load_stage(2);

    for (int i = 0; i < nk; i++) {
        int rem = nk - 1 - i;
        if (rem >= 2)      asm volatile("cp.async.wait_group 2;\n" ::);
        else if (rem == 1) asm volatile("cp.async.wait_group 1;\n" ::);
        else               asm volatile("cp.async.wait_group 0;\n" ::);
        __syncthreads();
        if (i + 3 < nk) load_stage(i + 3);

        uint32_t sb = sb0 + (uint32_t)(i % F1_NSTAGE) * F1_STAGE;
        #pragma unroll
        for (int s = 0; s < 2; s++) {
            uint32_t ah[2][4], bh[8][2];
            #pragma unroll
            for (int mt = 0; mt < 2; mt++)
                ldm_x4(ah[mt], sb + offA[mt][s]);
            #pragma unroll
            for (int pr = 0; pr < 4; pr++) {
                uint32_t t4[4];
                ldm_x4(t4, sb + 8192 + offB[pr][s]);
                bh[pr * 2][0] = t4[0]; bh[pr * 2][1] = t4[2];
                bh[pr * 2 + 1][0] = t4[1]; bh[pr * 2 + 1][1] = t4[3];
            }
            #pragma unroll
            for (int mt = 0; mt < 2; mt++)
                #pragma unroll
                for (int nt = 0; nt < 8; nt++)
                    mma16816(acc[mt][nt], ah[mt], bh[nt][0], bh[nt][1]);
        }
    }

    float* P = Pf + (size_t)blockIdx.z * M * N;
    int qr = lane >> 2, qc = (lane & 3) * 2;
    #pragma unroll
    for (int mt = 0; mt < 2; mt++) {
        int mlo = m0 + wm * 32 + mt * 16 + qr;
        #pragma unroll
        for (int nt = 0; nt < 8; nt++) {
            int nn = n0 + wn * 64 + nt * 8 + qc;
            if (mlo < M) {
                float2 vv; vv.x = acc[mt][nt][0]; vv.y = acc[mt][nt][1];
                *(float2*)(P + (size_t)mlo * N + nn) = vv;
            }
            if (mlo + 8 < M) {
                float2 vv; vv.x = acc[mt][nt][2]; vv.y = acc[mt][nt][3];
                *(float2*)(P + (size_t)(mlo + 8) * N + nn) = vv;
            }
        }
    }
}

// ---------------- FC2 GEMM: 128x256 tile, 3-term fp16 split ------------------
#define NSTAGE 3
#define F2_STAGE 49152

__global__ __launch_bounds__(256, 1) void gemm_fc2(
    const __half* __restrict__ Ahi, const __half* __restrict__ Alo,
    const __half* __restrict__ Bhi, const __half* __restrict__ Blo,
    float* __restrict__ Pf, int M, int N, int K, int kLen) {
    constexpr uint32_t ST_AH = 0, ST_AL = 8192, ST_BH = 16384, ST_BL = 32768;
    extern __shared__ char dynsmem[];
    uint32_t sb0 = smem_u32(dynsmem);

    int tid = threadIdx.x;
    int lane = tid & 31, wid = tid >> 5;
    int wm = wid >> 2, wn = wid & 3;
    int m0 = blockIdx.y * 128, n0 = blockIdx.x * 256;
    int kBase = blockIdx.z * kLen;

    int arow_l = tid >> 1;
    int lc = (tid & 1) * 2;
    int arow = min(m0 + arow_l, M - 1);
    const char* gAh = (const char*)(Ahi + (size_t)arow * K + kBase);
    const char* gAl = (const char*)(Alo + (size_t)arow * K + kBase);
    const char* gBh = (const char*)(Bhi + (size_t)(n0 + tid) * K + kBase);
    const char* gBl = (const char*)(Blo + (size_t)(n0 + tid) * K + kBase);
    uint32_t soA0 = sw64((uint32_t)(arow_l * 64 + lc * 16));
    uint32_t soA1 = sw64((uint32_t)(arow_l * 64 + (lc + 1) * 16));
    uint32_t soB[4];
    #pragma unroll
    for (int c = 0; c < 4; c++) soB[c] = sw64((uint32_t)(tid * 64 + c * 16));

    int nk = kLen >> 5;

    auto load_stage = [&](int j) {
        uint32_t sb = sb0 + (uint32_t)(j % NSTAGE) * F2_STAGE;
        int gbA = (j << 6) + (lc << 4);
        int gbB = (j << 6);
        cp16(sb + ST_AH + soA0, gAh + gbA);
        cp16(sb + ST_AH + soA1, gAh + gbA + 16);
        cp16(sb + ST_AL + soA0, gAl + gbA);
        cp16(sb + ST_AL + soA1, gAl + gbA + 16);
        #pragma unroll
        for (int c = 0; c < 4; c++) {
            cp16(sb + ST_BH + soB[c], gBh + gbB + c * 16);
            cp16(sb + ST_BL + soB[c], gBl + gbB + c * 16);
        }
        asm volatile("cp.async.commit_group;\n" ::);
    };

    int half = lane >> 4;
    int lr = lane & 15;
    uint32_t offA[4][2], offB[4][2];
    #pragma unroll
    for (int mt = 0; mt < 4; mt++)
        #pragma unroll
        for (int s = 0; s < 2; s++)
            offA[mt][s] = sw64((uint32_t)((wm * 64 + mt * 16 + lr) * 64 + (s * 2 + half) * 16));
    #pragma unroll
    for (int pr = 0; pr < 4; pr++)
        #pragma unroll
        for (int s = 0; s < 2; s++)
            offB[pr][s] = sw64((uint32_t)((wn * 64 + pr * 16 + lr) * 64 + (s * 2 + half) * 16));

    float acc[4][8][4];
    #pragma unroll
    for (int a = 0; a < 4; a++)
        #pragma unroll
        for (int b = 0; b < 8; b++)
            #pragma unroll
            for (int c = 0; c < 4; c++) acc[a][b][c] = 0.f;

    load_stage(0);
    load_stage(1);

    for (int i = 0; i < nk; i++) {
        if (i + 1 < nk) asm volatile("cp.async.wait_group 1;\n" ::);
        else            asm volatile("cp.async.wait_group 0;\n" ::);
        __syncthreads();
        if (i + 2 < nk) load_stage(i + 2);

        uint32_t sb = sb0 + (uint32_t)(i % NSTAGE) * F2_STAGE;
        #pragma unroll
        for (int s = 0; s < 2; s++) {
            uint32_t ah[4][4], al[4][4];
            uint32_t bh[8][2], bl[8][2];
            #pragma unroll
            for (int mt = 0; mt < 4; mt++) {
                ldm_x4(ah[mt], sb + ST_AH + offA[mt][s]);
                ldm_x4(al[mt], sb + ST_AL + offA[mt][s]);
            }
            #pragma unroll
            for (int pr = 0; pr < 4; pr++) {
                uint32_t t4[4];
                ldm_x4(t4, sb + ST_BH + offB[pr][s]);
                bh[pr * 2][0] = t4[0]; bh[pr * 2][1] = t4[2];
                bh[pr * 2 + 1][0] = t4[1]; bh[pr * 2 + 1][1] = t4[3];
                ldm_x4(t4, sb + ST_BL + offB[pr][s]);
                bl[pr * 2][0] = t4[0]; bl[pr * 2][1] = t4[2];
                bl[pr * 2 + 1][0] = t4[1]; bl[pr * 2 + 1][1] = t4[3];
            }
            #pragma unroll
            for (int mt = 0; mt < 4; mt++)
                #pragma unroll
                for (int nt = 0; nt < 8; nt++) {
                    mma16816(acc[mt][nt], ah[mt], bh[nt][0], bh[nt][1]);
                    mma16816(acc[mt][nt], al[mt], bh[nt][0], bh[nt][1]);
                    mma16816(acc[mt][nt], ah[mt], bl[nt][0], bl[nt][1]);
                }
        }
    }

    float* P = Pf + (size_t)blockIdx.z * M * N;
    int qr = lane >> 2, qc = (lane & 3) * 2;
    #pragma unroll
    for (int mt = 0; mt < 4; mt++) {
        int mlo = m0 + wm * 64 + mt * 16 + qr;
        #pragma unroll
        for (int nt = 0; nt < 8; nt++) {
            int nn = n0 + wn * 64 + nt * 8 + qc;
            if (mlo < M) {
                float2 vv; vv.x = acc[mt][nt][0]; vv.y = acc[mt][nt][1];
                *(float2*)(P + (size_t)mlo * N + nn) = vv;
            }
            if (mlo + 8 < M) {
                float2 vv; vv.x = acc[mt][nt][2]; vv.y = acc[mt][nt][3];
                *(float2*)(P + (size_t)(mlo + 8) * N + nn) = vv;
            }
        }
    }
}

// ---------------- FC1 reduce: sum partials + bias + relu -> x1 hi/lo ---------
__global__ __launch_bounds__(256) void reduce_fc1(
    const float* __restrict__ P, const float* __restrict__ bias,
    __half* __restrict__ Chi, __half* __restrict__ Clo, int MN, int N) {
    int i = blockIdx.x * 256 + threadIdx.x;
    if (i >= MN) return;
    float v = __ldg(bias + (i % N));
    #pragma unroll
    for (int z = 0; z < SPLITK; z++) v += P[(size_t)z * MN + i];
    v = fmaxf(v, 0.f);
    __half h = __float2half_rn(v);
    Chi[i] = h;
    Clo[i] = __float2half_rn(v - __half2float(h));
}

// ---------------- heads (fused FC2 reduce) -----------------------------------
__global__ __launch_bounds__(448) void heads_kernel(
    const float* __restrict__ P2, const float* __restrict__ b2,
    const float* __restrict__ wb, const float* __restrict__ bb,
    const float* __restrict__ wc, const float* __restrict__ bc,
    const float* __restrict__ wr, const float* __restrict__ br,
    const float* __restrict__ wu, const float* __restrict__ bu,
    float* __restrict__ out) {
    __shared__ float xs[DDIM];
    int n = blockIdx.x;
    const int MN = NROIS * DDIM;
    for (int i = threadIdx.x; i < DDIM; i += blockDim.x) {
        float v = __ldg(b2 + i);
        #pragma unroll
        for (int z = 0; z < SPLITK; z++) v += P2[(size_t)z * MN + n * DDIM + i];
        xs[i] = fmaxf(v, 0.f);
    }
    __syncthreads();
    int wid = threadIdx.x >> 5, lane = threadIdx.x & 31;
    const float* wrow;
    float bv;
    if (wid < 8)       { wrow = wb + wid * DDIM;        bv = bb[wid]; }
    else if (wid < 10) { wrow = wc + (wid - 8) * DDIM;  bv = bc[wid - 8]; }
    else if (wid < 12) { wrow = wr + (wid - 10) * DDIM; bv = br[wid - 10]; }
    else               { wrow = wu + (wid - 12) * DDIM; bv = bu[wid - 12]; }
    float s = 0.f;
    for (int i = lane; i < DDIM; i += 32) s += xs[i] * wrow[i];
    #pragma unroll
    for (int o = 16; o; o >>= 1) s += __shfl_down_sync(0xffffffff, s, o);
    if (lane == 0) {
        float v = s + bv;
        if (wid < 8)       out[n * 8 + wid] = v;
        else if (wid < 10) out[8000 + n * 2 + (wid - 8)] = v;
        else if (wid < 12) out[10000 + n * 4 + (wid - 10) * 2 + 0] = v;
        else               out[10000 + n * 4 + (wid - 12) * 2 + 1] = v;
    }
}

// ---------------- host launcher ---------------------------------------------
extern "C" void kernel_launch(void* const* d_in, const int* in_sizes, int n_in,
                              void* d_out, int out_size) {
    const float* fmap0 = (const float*)d_in[0];
    const float* fmap1 = (const float*)d_in[1];
    const float* fmap2 = (const float*)d_in[2];
    const float* fmap3 = (const float*)d_in[3];
    const float* rois  = (const float*)d_in[4];
    const float* w1    = (const float*)d_in[5];
    const float* b1    = (const float*)d_in[6];
    const float* w2    = (const float*)d_in[7];
    const float* b2    = (const float*)d_in[8];
    const float* wbbox = (const float*)d_in[9];
    const float* bbbox = (const float*)d_in[10];
    const float* wcls  = (const float*)d_in[11];
    const float* bcls  = (const float*)d_in[12];
    const float* wreg  = (const float*)d_in[13];
    const float* breg  = (const float*)d_in[14];
    const float* wunc  = (const float*)d_in[15];
    const float* bunc  = (const float*)d_in[16];
    float* out = (float*)d_out;

    __half *ph, *w1h, *w2h, *w2l, *x1h, *x1l;
    cudaGetSymbolAddress((void**)&ph,  g_ph);
    cudaGetSymbolAddress((void**)&w1h, g_w1h);
    cudaGetSymbolAddress((void**)&w2h, g_w2h);
    cudaGetSymbolAddress((void**)&w2l, g_w2l);
    cudaGetSymbolAddress((void**)&x1h, g_x1h);
    cudaGetSymbolAddress((void**)&x1l, g_x1l);
    float* part; cudaGetSymbolAddress((void**)&part, g_part);

    cudaFuncSetAttribute(gemm_fc1, cudaFuncAttributeMaxDynamicSharedMemorySize, F1_NSTAGE * F1_STAGE);
    cudaFuncSetAttribute(gemm_fc2, cudaFuncAttributeMaxDynamicSharedMemorySize, NSTAGE * F2_STAGE);

    // Lazy-created side stream + events (created on the uncaptured correctness
    // call; reused — not created — during graph capture).
    static cudaStream_t s1 = nullptr;
    static cudaEvent_t evFork = nullptr, evJoin = nullptr;
    if (s1 == nullptr) {
        cudaStreamCreateWithFlags(&s1, cudaStreamNonBlocking);
        cudaEventCreateWithFlags(&evFork, cudaEventDisableTiming);
        cudaEventCreateWithFlags(&evJoin, cudaEventDisableTiming);
    }

    // Fork: weight prep on s1, concurrent with transpose + RoIAlign on main.
    cudaEventRecord(evFork, 0);
    cudaStreamWaitEvent(s1, evFork, 0);
    {
        int n1 = DDIM * K1 / 2;
        round_half_kernel<<<(n1 + 255) / 256, 256, 0, s1>>>(w1, w1h, n1);
        int n2 = DDIM * DDIM / 2;
        split_kernel<<<(n2 + 255) / 256, 256, 0, s1>>>(w2, w2h, w2l, n2);
    }
    cudaEventRecord(evJoin, s1);

    // Fused transpose: all 4 levels in one launch.
    transpose_all<<<TP_TOTAL, dim3(32, 8)>>>(fmap0, fmap1, fmap2, fmap3);

    roialign_kernel<<<NROIS, 192>>>(rois);

    // Join before FC1 (needs w1h).
    cudaStreamWaitEvent(0, evJoin, 0);

    const int MN = NROIS * DDIM;
    // FC1: single-term fp16, 128x128 tile, 2 CTAs/SM, 4-stage, split-K=6
    gemm_fc1<<<dim3(DDIM / 128, (NROIS + 127) / 128, SPLITK), 256, F1_NSTAGE * F1_STAGE>>>(
        ph, w1h, part, NROIS, DDIM, K1, K1 / SPLITK);
    reduce_fc1<<<(MN + 255) / 256, 256>>>(part, b1, x1h, x1l, MN, DDIM);

    // FC2: 3-term fp16 split, 128x256 tile, split-K=6
    gemm_fc2<<<dim3(DDIM / 256, (NROIS + 127) / 128, SPLITK), 256, NSTAGE * F2_STAGE>>>(
        x1h, x1l, w2h, w2l, part, NROIS, DDIM, DDIM, DDIM / SPLITK);

    // heads with fused FC2 reduce
    heads_kernel<<<NROIS, 448>>>(part, b2, wbbox, bbbox, wcls, bcls, wreg, breg,
                                 wunc, bunc, out);
}